// round 2
// baseline (speedup 1.0000x reference)
#include <cuda_runtime.h>
#include <math.h>

// Problem constants
#define BH   24          // B*H = 2*12
#define TT   2048        // sequence length
#define NN   256         // feature dim
#define CC   128         // chunk size
#define NCH  16          // number of chunks (TT/CC)

// ---------------- device scratch (static globals: sanctioned workaround) ----
__device__ float g_tabc[TT * (NN/2)];         // cos table [t][j]  (1 MB)
__device__ float g_tabs[TT * (NN/2)];         // sin table          (1 MB)
__device__ float g_QR[BH * TT * NN];          // roped Q (50 MB)
__device__ float g_KR[BH * TT * NN];          // roped K (50 MB)
__device__ float g_S [BH * NCH * NN * NN];    // chunk KV states -> exclusive prefix (100 MB)

// ---------------- kernel 1: RoPE phase tables -------------------------------
// freqs[n] = 1/theta^(q/N)/(2pi), theta=2^16, q=floor(n/2)*2 -> freq pair j:
// 2^(-j/8)/(2pi). Mimic reference fp32 rounding: f32 freq, f32 t*f, f32 frac.
__global__ void k_tables() {
    int id = blockIdx.x * blockDim.x + threadIdx.x;   // 262144 threads
    if (id >= TT * (NN/2)) return;
    int t = id >> 7;          // 0..2047
    int j = id & 127;         // pair index
    double fr_d = exp2(-(double)j / 8.0) / (2.0 * 3.14159265358979323846);
    float f32   = (float)fr_d;                 // reference stores freq in f32
    float ph    = (float)t * f32;              // f32 multiply like reference
    ph          = ph - floorf(ph);             // f32 frac (% 1.0)
    float ang   = ph * 6.28318530717958647692f; // f32 * f32(2pi)
    double angd = (double)ang;
    g_tabc[id] = (float)cos(angd);
    g_tabs[id] = (float)sin(angd);
}

// ---------------- kernel 2: apply RoPE to Q and K ---------------------------
__global__ void k_rope(const float* __restrict__ Q, const float* __restrict__ K) {
    int idx = blockIdx.x * blockDim.x + threadIdx.x;
    const int per = BH * TT * (NN/2);          // 6291456 pairs per tensor
    if (idx >= 2 * per) return;
    int which = idx >= per;
    int i = idx - which * per;
    int n2 = i & 127;
    int t  = (i >> 7) & 2047;
    int bh = i >> 18;
    int off = (bh * TT + t) * NN + 2 * n2;
    const float* src = which ? K : Q;
    float*       dst = which ? g_KR : g_QR;
    float2 v = *(const float2*)(src + off);
    float c = g_tabc[t * 128 + n2];
    float s = g_tabs[t * 128 + n2];
    float2 r;
    r.x = v.x * c - v.y * s;   // even: v*cos - v_odd*sin
    r.y = v.y * c + v.x * s;   // odd : v*cos + v_even*sin
    *(float2*)(dst + off) = r;
}

// ---------------- kernel 3: per-chunk S = KR^T @ V (128x128 blocks) ---------
// grid: (BH*NCH, 4), block 256 (16x16), 8x8 per thread
__global__ void k_chunk_kv(const float* __restrict__ V) {
    int bx = blockIdx.x;
    int bh = bx >> 4, ch = bx & 15;
    int m0 = (blockIdx.y >> 1) * 128;
    int n0 = (blockIdx.y & 1) * 128;
    int t0 = ch * CC;

    __shared__ float as[16][128];
    __shared__ float bs[16][128];

    int tid = threadIdx.x;
    int ty = tid >> 4, tx = tid & 15;

    const float* KRp = g_KR + (bh * TT + t0) * NN;
    const float* Vp  = V    + (size_t)(bh * TT + t0) * NN;

    float acc[8][8];
#pragma unroll
    for (int i = 0; i < 8; i++)
#pragma unroll
        for (int j = 0; j < 8; j++) acc[i][j] = 0.f;

    for (int ks = 0; ks < CC; ks += 16) {
#pragma unroll
        for (int l = 0; l < 2; l++) {
            int idx = tid + l * 256;            // 0..511
            int ss = idx >> 5;
            int c4 = (idx & 31) << 2;
            *(float4*)&as[ss][c4] = *(const float4*)(KRp + (ks + ss) * NN + m0 + c4);
            *(float4*)&bs[ss][c4] = *(const float4*)(Vp  + (ks + ss) * NN + n0 + c4);
        }
        __syncthreads();
#pragma unroll
        for (int kk = 0; kk < 16; kk++) {
            float a[8], b[8];
            *(float4*)&a[0] = *(float4*)&as[kk][ty * 8];
            *(float4*)&a[4] = *(float4*)&as[kk][ty * 8 + 4];
            *(float4*)&b[0] = *(float4*)&bs[kk][tx * 8];
            *(float4*)&b[4] = *(float4*)&bs[kk][tx * 8 + 4];
#pragma unroll
            for (int i = 0; i < 8; i++)
#pragma unroll
                for (int j = 0; j < 8; j++)
                    acc[i][j] = fmaf(a[i], b[j], acc[i][j]);
        }
        __syncthreads();
    }

    float* Sp = g_S + (size_t)(bh * NCH + ch) * (NN * NN);
#pragma unroll
    for (int i = 0; i < 8; i++) {
        int row = m0 + ty * 8 + i;
        *(float4*)&Sp[row * NN + n0 + tx * 8]     = *(float4*)&acc[i][0];
        *(float4*)&Sp[row * NN + n0 + tx * 8 + 4] = *(float4*)&acc[i][4];
    }
}

// ---------------- kernel 4: exclusive prefix scan over chunks (in place) ----
__global__ void k_scan() {
    int g = blockIdx.x * blockDim.x + threadIdx.x;    // 24*65536 lanes
    if (g >= BH * NN * NN) return;
    int bh = g >> 16;
    int e  = g & 65535;
    size_t base = (size_t)bh * NCH * (NN * NN) + e;
    float run = 0.f;
#pragma unroll
    for (int i = 0; i < NCH; i++) {
        float v = g_S[base + (size_t)i * (NN * NN)];
        g_S[base + (size_t)i * (NN * NN)] = run;
        run += v;
    }
}

// ---------------- kernel 5: per-chunk output --------------------------------
// Out_i = QR_i @ S_pref_i + strict_tril(QR_i @ KR_i^T) @ V_i
// grid 384, block 512 (ty=tid/32 in [0,16), tx=tid%32), 8x8 acc -> 128x256 tile
#define PS_STRIDE 132
#define AT_STRIDE 132
#define BT_STRIDE 260
#define SMEM_FLOATS (128*PS_STRIDE + 16*AT_STRIDE + 16*BT_STRIDE)

__global__ void k_attn(const float* __restrict__ V, float* __restrict__ out) {
    extern __shared__ float sm[];
    float* Ps = sm;                                   // [128][132]
    float* at = sm + 128 * PS_STRIDE;                 // [16][132]
    float* bt = sm + 128 * PS_STRIDE + 16 * AT_STRIDE;// [16][260]

    int bx = blockIdx.x;
    int bh = bx >> 4, ch = bx & 15;
    int t0 = ch * CC;
    int tid = threadIdx.x;
    int ty = tid >> 5;        // 0..15
    int tx = tid & 31;        // 0..31

    const float* QRp = g_QR + (bh * TT + t0) * NN;
    const float* KRp = g_KR + (bh * TT + t0) * NN;

    // ---- Stage P: P = QR_i @ KR_i^T (128x128), per-thread 8x4 -------------
    float p[8][4];
#pragma unroll
    for (int i = 0; i < 8; i++)
#pragma unroll
        for (int j = 0; j < 4; j++) p[i][j] = 0.f;

    int lr = tid >> 2;             // loader row 0..127
    int lk4 = (tid & 3) << 2;      // loader k offset

    for (int ks = 0; ks < NN; ks += 16) {
        // transpose-load QR slab -> at[kk][r], KR slab -> bt[kk][c]
        float4 va = *(const float4*)(QRp + lr * NN + ks + lk4);
        float4 vb = *(const float4*)(KRp + lr * NN + ks + lk4);
        at[(lk4 + 0) * AT_STRIDE + lr] = va.x;
        at[(lk4 + 1) * AT_STRIDE + lr] = va.y;
        at[(lk4 + 2) * AT_STRIDE + lr] = va.z;
        at[(lk4 + 3) * AT_STRIDE + lr] = va.w;
        bt[(lk4 + 0) * BT_STRIDE + lr] = vb.x;
        bt[(lk4 + 1) * BT_STRIDE + lr] = vb.y;
        bt[(lk4 + 2) * BT_STRIDE + lr] = vb.z;
        bt[(lk4 + 3) * BT_STRIDE + lr] = vb.w;
        __syncthreads();
#pragma unroll
        for (int kk = 0; kk < 16; kk++) {
            float a[8], b4[4];
            *(float4*)&a[0]  = *(float4*)&at[kk * AT_STRIDE + ty * 8];
            *(float4*)&a[4]  = *(float4*)&at[kk * AT_STRIDE + ty * 8 + 4];
            *(float4*)&b4[0] = *(float4*)&bt[kk * BT_STRIDE + tx * 4];
#pragma unroll
            for (int i = 0; i < 8; i++)
#pragma unroll
                for (int j = 0; j < 4; j++)
                    p[i][j] = fmaf(a[i], b4[j], p[i][j]);
        }
        __syncthreads();
    }
    // masked write: keep s < t  (strict lower triangle)
#pragma unroll
    for (int i = 0; i < 8; i++) {
        int r = ty * 8 + i;
#pragma unroll
        for (int j = 0; j < 4; j++) {
            int c = tx * 4 + j;
            Ps[r * PS_STRIDE + c] = (c < r) ? p[i][j] : 0.f;
        }
    }
    __syncthreads();

    // ---- Stage G: acc = QR_i @ S_pref + Ps @ V_i ---------------------------
    float acc[8][8];
#pragma unroll
    for (int i = 0; i < 8; i++)
#pragma unroll
        for (int j = 0; j < 8; j++) acc[i][j] = 0.f;

    // GEMM 1: QR_i (128x256) @ S_pref (256x256)
    const float* Sp = g_S + (size_t)(bh * NCH + ch) * (NN * NN);
    for (int ks = 0; ks < NN; ks += 16) {
        float4 va = *(const float4*)(QRp + lr * NN + ks + lk4);
        at[(lk4 + 0) * AT_STRIDE + lr] = va.x;
        at[(lk4 + 1) * AT_STRIDE + lr] = va.y;
        at[(lk4 + 2) * AT_STRIDE + lr] = va.z;
        at[(lk4 + 3) * AT_STRIDE + lr] = va.w;
#pragma unroll
        for (int l = 0; l < 2; l++) {
            int idx = tid + l * 512;       // 0..1023
            int kk = idx >> 6;
            int c4 = (idx & 63) << 2;
            *(float4*)&bt[kk * BT_STRIDE + c4] =
                *(const float4*)(Sp + (ks + kk) * NN + c4);
        }
        __syncthreads();
#pragma unroll
        for (int kk = 0; kk < 16; kk++) {
            float a[8], b[8];
            *(float4*)&a[0] = *(float4*)&at[kk * AT_STRIDE + ty * 8];
            *(float4*)&a[4] = *(float4*)&at[kk * AT_STRIDE + ty * 8 + 4];
            *(float4*)&b[0] = *(float4*)&bt[kk * BT_STRIDE + tx * 8];
            *(float4*)&b[4] = *(float4*)&bt[kk * BT_STRIDE + tx * 8 + 4];
#pragma unroll
            for (int i = 0; i < 8; i++)
#pragma unroll
                for (int j = 0; j < 8; j++)
                    acc[i][j] = fmaf(a[i], b[j], acc[i][j]);
        }
        __syncthreads();
    }

    // GEMM 2: Ps (128x128, in smem) @ V_i (128x256)
    const float* Vp = V + (size_t)(bh * TT + t0) * NN;
    for (int ks = 0; ks < CC; ks += 16) {
#pragma unroll
        for (int l = 0; l < 2; l++) {
            int idx = tid + l * 512;
            int kk = idx >> 6;
            int c4 = (idx & 63) << 2;
            *(float4*)&bt[kk * BT_STRIDE + c4] =
                *(const float4*)(Vp + (ks + kk) * NN + c4);
        }
        __syncthreads();
#pragma unroll
        for (int kk = 0; kk < 16; kk++) {
            float b[8];
            *(float4*)&b[0] = *(float4*)&bt[kk * BT_STRIDE + tx * 8];
            *(float4*)&b[4] = *(float4*)&bt[kk * BT_STRIDE + tx * 8 + 4];
#pragma unroll
            for (int i = 0; i < 8; i++) {
                float a = Ps[(ty * 8 + i) * PS_STRIDE + ks + kk];
#pragma unroll
                for (int j = 0; j < 8; j++)
                    acc[i][j] = fmaf(a, b[j], acc[i][j]);
            }
        }
        __syncthreads();
    }

    // write output
    float* Op = out + (size_t)(bh * TT + t0) * NN;
#pragma unroll
    for (int i = 0; i < 8; i++) {
        int row = ty * 8 + i;
        *(float4*)&Op[row * NN + tx * 8]     = *(float4*)&acc[i][0];
        *(float4*)&Op[row * NN + tx * 8 + 4] = *(float4*)&acc[i][4];
    }
}

// ---------------- launcher ---------------------------------------------------
extern "C" void kernel_launch(void* const* d_in, const int* in_sizes, int n_in,
                              void* d_out, int out_size) {
    const float* Q = (const float*)d_in[0];
    const float* K = (const float*)d_in[1];
    const float* V = (const float*)d_in[2];
    float* out = (float*)d_out;

    static bool attr_set = false;
    if (!attr_set) {
        cudaFuncSetAttribute(k_attn, cudaFuncAttributeMaxDynamicSharedMemorySize,
                             SMEM_FLOATS * (int)sizeof(float));
        attr_set = true;
    }

    // 1. phase tables (262144 threads)
    k_tables<<<512, 512>>>();
    // 2. RoPE Q,K (2 * 6291456 pairs)
    int rope_total = 2 * BH * TT * (NN / 2);
    k_rope<<<(rope_total + 255) / 256, 256>>>(Q, K);
    // 3. per-chunk KV states
    k_chunk_kv<<<dim3(BH * NCH, 4), 256>>>(V);
    // 4. exclusive scan over chunks
    k_scan<<<(BH * NN * NN) / 256, 256>>>();
    // 5. outputs
    k_attn<<<BH * NCH, 512, SMEM_FLOATS * (int)sizeof(float)>>>(V, out);
}

// round 4
// speedup vs baseline: 1.6726x; 1.6726x over previous
#include <cuda_runtime.h>
#include <cuda_bf16.h>
#include <math.h>
#include <stdint.h>

#define BH   24
#define TT   2048
#define NN   256
#define CC   128
#define NCH  16

// ---------------- device scratch ----------------------------------------------
__device__ float g_tabc[TT * (NN/2)];
__device__ float g_tabs[TT * (NN/2)];
__device__ __nv_bfloat16 g_Qh[BH*TT*NN], g_Ql[BH*TT*NN];
__device__ __nv_bfloat16 g_Kh[BH*TT*NN], g_Kl[BH*TT*NN];
__device__ __nv_bfloat16 g_Vh[BH*TT*NN], g_Vl[BH*TT*NN];
__device__ float g_S[BH*NCH*NN*NN];                       // per-chunk K^T V sums (fp32)
__device__ __nv_bfloat16 g_Sh[BH*NCH*NN*NN], g_Sl[BH*NCH*NN*NN]; // exclusive prefix, bf16 hi/lo

// ---------------- PTX helpers (baseline sm_80+ features only) ------------------
__device__ __forceinline__ uint32_t smem_u32(const void* p) {
    uint32_t a;
    asm("{ .reg .u64 t; cvta.to.shared.u64 t, %1; cvt.u32.u64 %0, t; }" : "=r"(a) : "l"(p));
    return a;
}
__device__ __forceinline__ void cpa16(uint32_t s, const void* g) {
    asm volatile("cp.async.cg.shared.global [%0], [%1], 16;" :: "r"(s), "l"(g));
}
#define CP_COMMIT() asm volatile("cp.async.commit_group;" ::: "memory")
#define CP_WAIT0()  asm volatile("cp.async.wait_group 0;" ::: "memory")

__device__ __forceinline__ void ldsm4(uint32_t* r, uint32_t a) {
    asm volatile("ldmatrix.sync.aligned.m8n8.x4.shared.b16 {%0,%1,%2,%3}, [%4];"
        : "=r"(r[0]), "=r"(r[1]), "=r"(r[2]), "=r"(r[3]) : "r"(a));
}
__device__ __forceinline__ void ldsm4t(uint32_t* r, uint32_t a) {
    asm volatile("ldmatrix.sync.aligned.m8n8.x4.trans.shared.b16 {%0,%1,%2,%3}, [%4];"
        : "=r"(r[0]), "=r"(r[1]), "=r"(r[2]), "=r"(r[3]) : "r"(a));
}
__device__ __forceinline__ void mma_bf16(float* d, const uint32_t* a, const uint32_t* b) {
    asm volatile("mma.sync.aligned.m16n8k16.row.col.f32.bf16.bf16.f32 "
        "{%0,%1,%2,%3}, {%4,%5,%6,%7}, {%8,%9}, {%0,%1,%2,%3};"
        : "+f"(d[0]), "+f"(d[1]), "+f"(d[2]), "+f"(d[3])
        : "r"(a[0]), "r"(a[1]), "r"(a[2]), "r"(a[3]), "r"(b[0]), "r"(b[1]));
}

// ---------------- kernel 1: RoPE phase tables ----------------------------------
__global__ void k_tables() {
    int id = blockIdx.x * blockDim.x + threadIdx.x;
    if (id >= TT * (NN/2)) return;
    int t = id >> 7;
    int j = id & 127;
    double fr_d = exp2(-(double)j / 8.0) / (2.0 * 3.14159265358979323846);
    float f32 = (float)fr_d;
    float ph  = (float)t * f32;
    ph = ph - floorf(ph);
    float ang = ph * 6.28318530717958647692f;
    double angd = (double)ang;
    g_tabc[id] = (float)cos(angd);
    g_tabs[id] = (float)sin(angd);
}

// ---------------- kernel 2: RoPE(Q,K) + bf16 hi/lo split; split V --------------
__global__ void k_prep(const float* __restrict__ Q, const float* __restrict__ K,
                       const float* __restrict__ V) {
    int idx = blockIdx.x * blockDim.x + threadIdx.x;
    const int per = BH * TT * (NN/2);
    if (idx >= 3 * per) return;
    int which = idx / per;               // 0=Q 1=K 2=V
    int i = idx - which * per;
    int n2 = i & 127;
    int t  = (i >> 7) & 2047;
    int bh = i >> 18;
    int off = (bh * TT + t) * NN + 2 * n2;
    const float* src = (which == 0) ? Q : (which == 1) ? K : V;
    float2 v = *(const float2*)(src + off);
    float2 r;
    if (which < 2) {
        float c = g_tabc[t * 128 + n2];
        float s = g_tabs[t * 128 + n2];
        r.x = v.x * c - v.y * s;
        r.y = v.y * c + v.x * s;
    } else r = v;
    __nv_bfloat16 hx = __float2bfloat16(r.x);
    __nv_bfloat16 hy = __float2bfloat16(r.y);
    __nv_bfloat16 lx = __float2bfloat16(r.x - __bfloat162float(hx));
    __nv_bfloat16 ly = __float2bfloat16(r.y - __bfloat162float(hy));
    __nv_bfloat16* dh = (which == 0) ? g_Qh : (which == 1) ? g_Kh : g_Vh;
    __nv_bfloat16* dl = (which == 0) ? g_Ql : (which == 1) ? g_Kl : g_Vl;
    __nv_bfloat162 ph2; ph2.x = hx; ph2.y = hy;
    __nv_bfloat162 pl2; pl2.x = lx; pl2.y = ly;
    *(__nv_bfloat162*)(dh + off) = ph2;
    *(__nv_bfloat162*)(dl + off) = pl2;
}

// ---------------- fragment-address lane constants ------------------------------
// A non-trans  (row-major [m][k], stride s): off = (m0 + lm16)*s + k0 + 8*l16
// A trans      (storage [k][m],  stride s): off = (k0 + lmod8 + 8*l16)*s + m0 + 8*l8
// B pair non-t (storage [n][k],  stride s): off = (n0 + lmod8 + 8*l16)*s + k0 + 8*l8
// B pair trans (storage [k][n],  stride s): off = (k0 + lmod8 + 8*l8)*s + n0 + 8*l16

// ---------------- kernel 3: chunk KV state S_ch = KR^T @ V ----------------------
// grid (BH*15, 2): bh=bx/15, ch=bx%15, m0g = by*128. CTA out tile 128x256 (fp32).
#define KV_AH 0
#define KV_AL 8704
#define KV_B_H 17408
#define KV_B_L 34304
#define SMEM_KV 51200

__global__ void __launch_bounds__(256, 1) k_kv() {
    extern __shared__ char sm[];
    uint32_t sb = smem_u32(sm);
    int tid = threadIdx.x, lane = tid & 31, wid = tid >> 5;
    int wm = wid >> 2, wn = wid & 3;
    int bx = blockIdx.x;
    int bh = bx / 15, ch = bx % 15;
    int m0g = blockIdx.y * 128;
    int t0 = ch * CC;
    int lm16 = lane & 15, l16 = lane >> 4, lmod8 = lane & 7, l8 = (lane >> 3) & 1;
    int lq = lane >> 2, lr2 = (lane & 3) * 2;

    const __nv_bfloat16* Kh = g_Kh + (size_t)(bh * TT + t0) * NN;
    const __nv_bfloat16* Kl = g_Kl + (size_t)(bh * TT + t0) * NN;
    const __nv_bfloat16* Vh = g_Vh + (size_t)(bh * TT + t0) * NN;
    const __nv_bfloat16* Vl = g_Vl + (size_t)(bh * TT + t0) * NN;

    float acc[4][8][4];
#pragma unroll
    for (int a = 0; a < 4; a++)
#pragma unroll
        for (int b = 0; b < 8; b++)
#pragma unroll
            for (int c = 0; c < 4; c++) acc[a][b][c] = 0.f;

    for (int sl = 0; sl < 4; sl++) {
        // stage A = KR rows (t) x cols (m0g..m0g+128): [32][128], stride 136 b16
        {
            const __nv_bfloat16* gH = Kh + (size_t)sl * 32 * NN + m0g;
            const __nv_bfloat16* gL = Kl + (size_t)sl * 32 * NN + m0g;
            for (int v = tid; v < 512; v += 256) {
                int r = v >> 4, c8 = v & 15;
                uint32_t so = (uint32_t)(r * 272 + c8 * 16);
                cpa16(sb + KV_AH + so, gH + (size_t)r * NN + c8 * 8);
                cpa16(sb + KV_AL + so, gL + (size_t)r * NN + c8 * 8);
            }
            const __nv_bfloat16* vH = Vh + (size_t)sl * 32 * NN;
            const __nv_bfloat16* vL = Vl + (size_t)sl * 32 * NN;
            for (int v = tid; v < 1024; v += 256) {
                int r = v >> 5, c8 = v & 31;
                uint32_t so = (uint32_t)(r * 528 + c8 * 16);
                cpa16(sb + KV_B_H + so, vH + (size_t)r * NN + c8 * 8);
                cpa16(sb + KV_B_L + so, vL + (size_t)r * NN + c8 * 8);
            }
        }
        CP_COMMIT(); CP_WAIT0();
        __syncthreads();
#pragma unroll
        for (int k0 = 0; k0 < 32; k0 += 16) {
            uint32_t ah[4][4], al[4][4];
#pragma unroll
            for (int mt = 0; mt < 4; mt++) {
                uint32_t off = (uint32_t)(((k0 + lmod8 + 8 * l16) * 136 +
                                           wm * 64 + mt * 16 + 8 * l8) * 2);
                ldsm4t(ah[mt], sb + KV_AH + off);
                ldsm4t(al[mt], sb + KV_AL + off);
            }
#pragma unroll
            for (int np = 0; np < 4; np++) {
                uint32_t bh2[4], bl2[4];
                uint32_t off = (uint32_t)(((k0 + lmod8 + 8 * l8) * 264 +
                                           wn * 64 + np * 16 + 8 * l16) * 2);
                ldsm4t(bh2, sb + KV_B_H + off);
                ldsm4t(bl2, sb + KV_B_L + off);
#pragma unroll
                for (int mt = 0; mt < 4; mt++) {
                    mma_bf16(acc[mt][2*np],   ah[mt], bh2);
                    mma_bf16(acc[mt][2*np],   ah[mt], bl2);
                    mma_bf16(acc[mt][2*np],   al[mt], bh2);
                    mma_bf16(acc[mt][2*np+1], ah[mt], bh2 + 2);
                    mma_bf16(acc[mt][2*np+1], ah[mt], bl2 + 2);
                    mma_bf16(acc[mt][2*np+1], al[mt], bh2 + 2);
                }
            }
        }
        __syncthreads();
    }
    float* Sp = g_S + (size_t)(bh * NCH + ch) * (NN * NN);
#pragma unroll
    for (int mt = 0; mt < 4; mt++)
#pragma unroll
        for (int nt = 0; nt < 8; nt++)
#pragma unroll
            for (int h = 0; h < 2; h++) {
                int rr = m0g + wm * 64 + mt * 16 + lq + 8 * h;
                int cc = wn * 64 + nt * 8 + lr2;
                float2 o; o.x = acc[mt][nt][2*h]; o.y = acc[mt][nt][2*h+1];
                *(float2*)(Sp + (size_t)rr * NN + cc) = o;
            }
}

// ---------------- kernel 4: exclusive prefix scan + bf16 split -----------------
__global__ void k_scan() {
    int g = blockIdx.x * blockDim.x + threadIdx.x;
    if (g >= BH * NN * NN) return;
    int bh = g >> 16;
    int e  = g & 65535;
    size_t base = (size_t)bh * NCH * (NN * NN) + e;
    float run = 0.f;
#pragma unroll
    for (int i = 0; i < NCH; i++) {
        size_t p = base + (size_t)i * (NN * NN);
        float v = (i < NCH - 1) ? g_S[p] : 0.f;
        __nv_bfloat16 h = __float2bfloat16(run);
        g_Sh[p] = h;
        g_Sl[p] = __float2bfloat16(run - __bfloat162float(h));
        run += v;
    }
}

// ---------------- kernel 5: Out = QR@S_pref + strict_tril(QR@KR^T)@V -----------
#define AT_AH 0
#define AT_AL 10240
#define AT_B_H 20480
#define AT_B_L 37376
#define AT_PH 54272
#define AT_PL 89088
#define SMEM_ATTN 123904

__global__ void __launch_bounds__(256, 1) k_attn(float* __restrict__ out) {
    extern __shared__ char sm[];
    uint32_t sb = smem_u32(sm);
    int tid = threadIdx.x, lane = tid & 31, wid = tid >> 5;
    int wm = wid >> 2, wn = wid & 3;
    int bh = blockIdx.x >> 4, ch = blockIdx.x & 15;
    int t0 = ch * CC;
    int lm16 = lane & 15, l16 = lane >> 4, lmod8 = lane & 7, l8 = (lane >> 3) & 1;
    int lq = lane >> 2, lr2 = (lane & 3) * 2;

    const __nv_bfloat16* Qh = g_Qh + (size_t)(bh * TT + t0) * NN;
    const __nv_bfloat16* Ql = g_Ql + (size_t)(bh * TT + t0) * NN;
    const __nv_bfloat16* Kh = g_Kh + (size_t)(bh * TT + t0) * NN;
    const __nv_bfloat16* Kl = g_Kl + (size_t)(bh * TT + t0) * NN;
    const __nv_bfloat16* Vh = g_Vh + (size_t)(bh * TT + t0) * NN;
    const __nv_bfloat16* Vl = g_Vl + (size_t)(bh * TT + t0) * NN;
    const __nv_bfloat16* Sh = g_Sh + (size_t)(bh * NCH + ch) * (NN * NN);
    const __nv_bfloat16* Sl = g_Sl + (size_t)(bh * NCH + ch) * (NN * NN);

    // ======== Stage 1: P = QR @ KR^T (128x128), warp tile 64x32 ===============
    {
        float acc1[4][4][4];
#pragma unroll
        for (int a = 0; a < 4; a++)
#pragma unroll
            for (int b = 0; b < 4; b++)
#pragma unroll
                for (int c = 0; c < 4; c++) acc1[a][b][c] = 0.f;

        for (int sl = 0; sl < 8; sl++) {
            int f0 = sl * 32;
            for (int v = tid; v < 512; v += 256) {           // Q slab [128][32] str 40
                int r = v >> 2, c8 = v & 3;
                uint32_t so = (uint32_t)(r * 80 + c8 * 16);
                cpa16(sb + AT_AH + so, Qh + (size_t)r * NN + f0 + c8 * 8);
                cpa16(sb + AT_AL + so, Ql + (size_t)r * NN + f0 + c8 * 8);
            }
            for (int v = tid; v < 512; v += 256) {           // K slab [128][32] str 40
                int r = v >> 2, c8 = v & 3;
                uint32_t so = (uint32_t)(r * 80 + c8 * 16);
                cpa16(sb + AT_B_H + so, Kh + (size_t)r * NN + f0 + c8 * 8);
                cpa16(sb + AT_B_L + so, Kl + (size_t)r * NN + f0 + c8 * 8);
            }
            CP_COMMIT(); CP_WAIT0();
            __syncthreads();
#pragma unroll
            for (int k0 = 0; k0 < 32; k0 += 16) {
                uint32_t ah[4][4], al[4][4];
#pragma unroll
                for (int mt = 0; mt < 4; mt++) {
                    uint32_t off = (uint32_t)(((wm * 64 + mt * 16 + lm16) * 40 +
                                               k0 + 8 * l16) * 2);
                    ldsm4(ah[mt], sb + AT_AH + off);
                    ldsm4(al[mt], sb + AT_AL + off);
                }
#pragma unroll
                for (int np = 0; np < 2; np++) {
                    uint32_t bh2[4], bl2[4];
                    uint32_t off = (uint32_t)(((wn * 32 + np * 16 + lmod8 + 8 * l16) * 40 +
                                               k0 + 8 * l8) * 2);
                    ldsm4(bh2, sb + AT_B_H + off);
                    ldsm4(bl2, sb + AT_B_L + off);
#pragma unroll
                    for (int mt = 0; mt < 4; mt++) {
                        mma_bf16(acc1[mt][2*np],   ah[mt], bh2);
                        mma_bf16(acc1[mt][2*np],   ah[mt], bl2);
                        mma_bf16(acc1[mt][2*np],   al[mt], bh2);
                        mma_bf16(acc1[mt][2*np+1], ah[mt], bh2 + 2);
                        mma_bf16(acc1[mt][2*np+1], ah[mt], bl2 + 2);
                        mma_bf16(acc1[mt][2*np+1], al[mt], bh2 + 2);
                    }
                }
            }
            __syncthreads();
        }
        // mask (strict lower triangle) + split to bf16 hi/lo in smem P
#pragma unroll
        for (int mt = 0; mt < 4; mt++)
#pragma unroll
            for (int nt = 0; nt < 4; nt++)
#pragma unroll
                for (int h = 0; h < 2; h++) {
                    int rr = wm * 64 + mt * 16 + lq + 8 * h;
                    int cn = wn * 32 + nt * 8 + lr2;
                    float v0 = (cn     < rr) ? acc1[mt][nt][2*h]   : 0.f;
                    float v1 = (cn + 1 < rr) ? acc1[mt][nt][2*h+1] : 0.f;
                    __nv_bfloat16 h0 = __float2bfloat16(v0);
                    __nv_bfloat16 h1 = __float2bfloat16(v1);
                    __nv_bfloat16 l0 = __float2bfloat16(v0 - __bfloat162float(h0));
                    __nv_bfloat16 l1 = __float2bfloat16(v1 - __bfloat162float(h1));
                    uint32_t bo = (uint32_t)((rr * 136 + cn) * 2);
                    __nv_bfloat162 ph2; ph2.x = h0; ph2.y = h1;
                    __nv_bfloat162 pl2; pl2.x = l0; pl2.y = l1;
                    *(__nv_bfloat162*)(sm + AT_PH + bo) = ph2;
                    *(__nv_bfloat162*)(sm + AT_PL + bo) = pl2;
                }
        __syncthreads();
    }

    // ======== Stages 2+3: D = QR@S_pref + P@V, warp tile 64x64 ================
    float acc[4][8][4];
#pragma unroll
    for (int a = 0; a < 4; a++)
#pragma unroll
        for (int b = 0; b < 8; b++)
#pragma unroll
            for (int c = 0; c < 4; c++) acc[a][b][c] = 0.f;

    if (ch > 0) {
        for (int sl = 0; sl < 8; sl++) {
            int f0 = sl * 32;
            for (int v = tid; v < 512; v += 256) {           // Q slab [128][32]
                int r = v >> 2, c8 = v & 3;
                uint32_t so = (uint32_t)(r * 80 + c8 * 16);
                cpa16(sb + AT_AH + so, Qh + (size_t)r * NN + f0 + c8 * 8);
                cpa16(sb + AT_AL + so, Ql + (size_t)r * NN + f0 + c8 * 8);
            }
            for (int v = tid; v < 1024; v += 256) {          // S slab [32][256] str 264
                int r = v >> 5, c8 = v & 31;
                uint32_t so = (uint32_t)(r * 528 + c8 * 16);
                cpa16(sb + AT_B_H + so, Sh + (size_t)(f0 + r) * NN + c8 * 8);
                cpa16(sb + AT_B_L + so, Sl + (size_t)(f0 + r) * NN + c8 * 8);
            }
            CP_COMMIT(); CP_WAIT0();
            __syncthreads();
#pragma unroll
            for (int k0 = 0; k0 < 32; k0 += 16) {
                uint32_t ah[4][4], al[4][4];
#pragma unroll
                for (int mt = 0; mt < 4; mt++) {
                    uint32_t off = (uint32_t)(((wm * 64 + mt * 16 + lm16) * 40 +
                                               k0 + 8 * l16) * 2);
                    ldsm4(ah[mt], sb + AT_AH + off);
                    ldsm4(al[mt], sb + AT_AL + off);
                }
#pragma unroll
                for (int np = 0; np < 4; np++) {
                    uint32_t bh2[4], bl2[4];
                    uint32_t off = (uint32_t)(((k0 + lmod8 + 8 * l8) * 264 +
                                               wn * 64 + np * 16 + 8 * l16) * 2);
                    ldsm4t(bh2, sb + AT_B_H + off);
                    ldsm4t(bl2, sb + AT_B_L + off);
#pragma unroll
                    for (int mt = 0; mt < 4; mt++) {
                        mma_bf16(acc[mt][2*np],   ah[mt], bh2);
                        mma_bf16(acc[mt][2*np],   ah[mt], bl2);
                        mma_bf16(acc[mt][2*np],   al[mt], bh2);
                        mma_bf16(acc[mt][2*np+1], ah[mt], bh2 + 2);
                        mma_bf16(acc[mt][2*np+1], ah[mt], bl2 + 2);
                        mma_bf16(acc[mt][2*np+1], al[mt], bh2 + 2);
                    }
                }
            }
            __syncthreads();
        }
    }

    // Stage 3: D += P @ V  (contraction over s = 128; A = P in smem)
    for (int sl = 0; sl < 4; sl++) {
        int s0 = sl * 32;
        for (int v = tid; v < 1024; v += 256) {              // V slab [32][256] str 264
            int r = v >> 5, c8 = v & 31;
            uint32_t so = (uint32_t)(r * 528 + c8 * 16);
            cpa16(sb + AT_B_H + so, Vh + (size_t)(s0 + r) * NN + c8 * 8);
            cpa16(sb + AT_B_L + so, Vl + (size_t)(s0 + r) * NN + c8 * 8);
        }
        CP_COMMIT(); CP_WAIT0();
        __syncthreads();
#pragma unroll
        for (int k0 = 0; k0 < 32; k0 += 16) {
            uint32_t ah[4][4], al[4][4];
#pragma unroll
            for (int mt = 0; mt < 4; mt++) {
                uint32_t off = (uint32_t)(((wm * 64 + mt * 16 + lm16) * 136 +
                                           s0 + k0 + 8 * l16) * 2);
                ldsm4(ah[mt], sb + AT_PH + off);
                ldsm4(al[mt], sb + AT_PL + off);
            }
#pragma unroll
            for (int np = 0; np < 4; np++) {
                uint32_t bh2[4], bl2[4];
                uint32_t off = (uint32_t)(((k0 + lmod8 + 8 * l8) * 264 +
                                           wn * 64 + np * 16 + 8 * l16) * 2);
                ldsm4t(bh2, sb + AT_B_H + off);
                ldsm4t(bl2, sb + AT_B_L + off);
#pragma unroll
                for (int mt = 0; mt < 4; mt++) {
                    mma_bf16(acc[mt][2*np],   ah[mt], bh2);
                    mma_bf16(acc[mt][2*np],   ah[mt], bl2);
                    mma_bf16(acc[mt][2*np],   al[mt], bh2);
                    mma_bf16(acc[mt][2*np+1], ah[mt], bh2 + 2);
                    mma_bf16(acc[mt][2*np+1], ah[mt], bl2 + 2);
                    mma_bf16(acc[mt][2*np+1], al[mt], bh2 + 2);
                }
            }
        }
        __syncthreads();
    }

    // epilogue: fp32 out
#pragma unroll
    for (int mt = 0; mt < 4; mt++)
#pragma unroll
        for (int nt = 0; nt < 8; nt++)
#pragma unroll
            for (int h = 0; h < 2; h++) {
                int rr = wm * 64 + mt * 16 + lq + 8 * h;
                int cc = wn * 64 + nt * 8 + lr2;
                float2 o; o.x = acc[mt][nt][2*h]; o.y = acc[mt][nt][2*h+1];
                *(float2*)(out + (size_t)(bh * TT + t0 + rr) * NN + cc) = o;
            }
}

// ---------------- launcher ------------------------------------------------------
extern "C" void kernel_launch(void* const* d_in, const int* in_sizes, int n_in,
                              void* d_out, int out_size) {
    const float* Q = (const float*)d_in[0];
    const float* K = (const float*)d_in[1];
    const float* V = (const float*)d_in[2];
    float* out = (float*)d_out;

    static bool attr_set = false;
    if (!attr_set) {
        cudaFuncSetAttribute(k_kv,   cudaFuncAttributeMaxDynamicSharedMemorySize, SMEM_KV);
        cudaFuncSetAttribute(k_attn, cudaFuncAttributeMaxDynamicSharedMemorySize, SMEM_ATTN);
        attr_set = true;
    }

    k_tables<<<512, 512>>>();
    int prep_total = 3 * BH * TT * (NN / 2);
    k_prep<<<(prep_total + 255) / 256, 256>>>(Q, K, V);
    k_kv<<<dim3(BH * (NCH - 1), 2), 256, SMEM_KV>>>();
    k_scan<<<(BH * NN * NN) / 256, 256>>>();
    k_attn<<<BH * NCH, 256, SMEM_ATTN>>>(out);
}

// round 5
// speedup vs baseline: 2.1112x; 1.2622x over previous
#include <cuda_runtime.h>
#include <cuda_bf16.h>
#include <math.h>
#include <stdint.h>

#define BH   24
#define TT   2048
#define NN   256
#define CC   128
#define NCH  16

// ---------------- device scratch ----------------------------------------------
__device__ float g_tabc[TT * (NN/2)];
__device__ float g_tabs[TT * (NN/2)];
__device__ __nv_bfloat16 g_Qh[BH*TT*NN], g_Ql[BH*TT*NN];
__device__ __nv_bfloat16 g_Kh[BH*TT*NN], g_Kl[BH*TT*NN];
__device__ __nv_bfloat16 g_Vh[BH*TT*NN], g_Vl[BH*TT*NN];
__device__ float g_S[BH*NCH*NN*NN];
__device__ __nv_bfloat16 g_Sh[BH*NCH*NN*NN], g_Sl[BH*NCH*NN*NN];

// ---------------- PTX helpers ---------------------------------------------------
__device__ __forceinline__ uint32_t smem_u32(const void* p) {
    uint32_t a;
    asm("{ .reg .u64 t; cvta.to.shared.u64 t, %1; cvt.u32.u64 %0, t; }" : "=r"(a) : "l"(p));
    return a;
}
__device__ __forceinline__ void cpa16(uint32_t s, const void* g) {
    asm volatile("cp.async.cg.shared.global [%0], [%1], 16;" :: "r"(s), "l"(g));
}
#define CP_COMMIT() asm volatile("cp.async.commit_group;" ::: "memory")
#define CP_WAIT0()  asm volatile("cp.async.wait_group 0;" ::: "memory")
#define CP_WAIT1()  asm volatile("cp.async.wait_group 1;" ::: "memory")

__device__ __forceinline__ void ldsm4(uint32_t* r, uint32_t a) {
    asm volatile("ldmatrix.sync.aligned.m8n8.x4.shared.b16 {%0,%1,%2,%3}, [%4];"
        : "=r"(r[0]), "=r"(r[1]), "=r"(r[2]), "=r"(r[3]) : "r"(a));
}
__device__ __forceinline__ void ldsm4t(uint32_t* r, uint32_t a) {
    asm volatile("ldmatrix.sync.aligned.m8n8.x4.trans.shared.b16 {%0,%1,%2,%3}, [%4];"
        : "=r"(r[0]), "=r"(r[1]), "=r"(r[2]), "=r"(r[3]) : "r"(a));
}
__device__ __forceinline__ void mma_bf16(float* d, const uint32_t* a, const uint32_t* b) {
    asm volatile("mma.sync.aligned.m16n8k16.row.col.f32.bf16.bf16.f32 "
        "{%0,%1,%2,%3}, {%4,%5,%6,%7}, {%8,%9}, {%0,%1,%2,%3};"
        : "+f"(d[0]), "+f"(d[1]), "+f"(d[2]), "+f"(d[3])
        : "r"(a[0]), "r"(a[1]), "r"(a[2]), "r"(a[3]), "r"(b[0]), "r"(b[1]));
}

// ---------------- kernel 1: RoPE phase tables -----------------------------------
__global__ void k_tables() {
    int id = blockIdx.x * blockDim.x + threadIdx.x;
    if (id >= TT * (NN/2)) return;
    int t = id >> 7;
    int j = id & 127;
    double fr_d = exp2(-(double)j / 8.0) / (2.0 * 3.14159265358979323846);
    float f32 = (float)fr_d;
    float ph  = (float)t * f32;
    ph = ph - floorf(ph);
    float ang = ph * 6.28318530717958647692f;
    double angd = (double)ang;
    g_tabc[id] = (float)cos(angd);
    g_tabs[id] = (float)sin(angd);
}

// ---------------- kernel 2: RoPE + bf16 hi/lo split (float4 vectorized) --------
__global__ void k_prep(const float* __restrict__ Q, const float* __restrict__ K,
                       const float* __restrict__ V) {
    int idx = blockIdx.x * blockDim.x + threadIdx.x;
    const int per = BH * TT * (NN/4);          // float4 groups per tensor
    if (idx >= 3 * per) return;
    int which = idx / per;
    int i = idx - which * per;
    int n4 = i & 63;
    int t  = (i >> 6) & 2047;
    int bh = i >> 17;
    int off = (bh * TT + t) * NN + 4 * n4;
    const float* src = (which == 0) ? Q : (which == 1) ? K : V;
    float4 v = *(const float4*)(src + off);
    float4 r;
    if (which < 2) {
        float c0 = g_tabc[t * 128 + 2*n4],     s0 = g_tabs[t * 128 + 2*n4];
        float c1 = g_tabc[t * 128 + 2*n4 + 1], s1 = g_tabs[t * 128 + 2*n4 + 1];
        r.x = v.x * c0 - v.y * s0;
        r.y = v.y * c0 + v.x * s0;
        r.z = v.z * c1 - v.w * s1;
        r.w = v.w * c1 + v.z * s1;
    } else r = v;
    __nv_bfloat16 h0 = __float2bfloat16(r.x), h1 = __float2bfloat16(r.y);
    __nv_bfloat16 h2 = __float2bfloat16(r.z), h3 = __float2bfloat16(r.w);
    __nv_bfloat16 l0 = __float2bfloat16(r.x - __bfloat162float(h0));
    __nv_bfloat16 l1 = __float2bfloat16(r.y - __bfloat162float(h1));
    __nv_bfloat16 l2 = __float2bfloat16(r.z - __bfloat162float(h2));
    __nv_bfloat16 l3 = __float2bfloat16(r.w - __bfloat162float(h3));
    __nv_bfloat16* dh = (which == 0) ? g_Qh : (which == 1) ? g_Kh : g_Vh;
    __nv_bfloat16* dl = (which == 0) ? g_Ql : (which == 1) ? g_Kl : g_Vl;
    __nv_bfloat162 H[2], L[2];
    H[0].x = h0; H[0].y = h1; H[1].x = h2; H[1].y = h3;
    L[0].x = l0; L[0].y = l1; L[1].x = l2; L[1].y = l3;
    *(uint2*)(dh + off) = *(uint2*)H;
    *(uint2*)(dl + off) = *(uint2*)L;
}

// ---------------- kernel 3: chunk KV state S_ch = KR^T @ V ----------------------
// double-buffered: A buf = [32][136]*2 (hi+lo) = 17408 B; B buf = [32][264]*2 = 33792 B
#define KV_BUF_A 17408
#define KV_BUF_B 33792
#define KV_B0    34816
#define SMEM_KV  102400

__global__ void __launch_bounds__(256, 1) k_kv() {
    extern __shared__ char sm[];
    uint32_t sb = smem_u32(sm);
    int tid = threadIdx.x, lane = tid & 31, wid = tid >> 5;
    int wm = wid >> 2, wn = wid & 3;
    int bx = blockIdx.x;
    int bh = bx / 15, ch = bx % 15;
    int m0g = blockIdx.y * 128;
    int t0 = ch * CC;
    int l16 = lane >> 4, lmod8 = lane & 7, l8 = (lane >> 3) & 1;
    int lq = lane >> 2, lr2 = (lane & 3) * 2;

    const __nv_bfloat16* Kh = g_Kh + (size_t)(bh * TT + t0) * NN;
    const __nv_bfloat16* Kl = g_Kl + (size_t)(bh * TT + t0) * NN;
    const __nv_bfloat16* Vh = g_Vh + (size_t)(bh * TT + t0) * NN;
    const __nv_bfloat16* Vl = g_Vl + (size_t)(bh * TT + t0) * NN;

    float acc[4][8][4];
#pragma unroll
    for (int a = 0; a < 4; a++)
#pragma unroll
        for (int b = 0; b < 8; b++)
#pragma unroll
            for (int c = 0; c < 4; c++) acc[a][b][c] = 0.f;

    // staging lambda-equivalents (macro-free, inline)
    auto stage = [&](int buf, int sl) {
        uint32_t abase = sb + buf * KV_BUF_A;
        const __nv_bfloat16* gH = Kh + (size_t)sl * 32 * NN + m0g;
        const __nv_bfloat16* gL = Kl + (size_t)sl * 32 * NN + m0g;
        for (int v = tid; v < 512; v += 256) {
            int r = v >> 4, c8 = v & 15;
            uint32_t so = (uint32_t)(r * 272 + c8 * 16);
            cpa16(abase + so,        gH + (size_t)r * NN + c8 * 8);
            cpa16(abase + 8704 + so, gL + (size_t)r * NN + c8 * 8);
        }
        uint32_t bbase = sb + KV_B0 + buf * KV_BUF_B;
        const __nv_bfloat16* vH = Vh + (size_t)sl * 32 * NN;
        const __nv_bfloat16* vL = Vl + (size_t)sl * 32 * NN;
        for (int v = tid; v < 1024; v += 256) {
            int r = v >> 5, c8 = v & 31;
            uint32_t so = (uint32_t)(r * 528 + c8 * 16);
            cpa16(bbase + so,         vH + (size_t)r * NN + c8 * 8);
            cpa16(bbase + 16896 + so, vL + (size_t)r * NN + c8 * 8);
        }
    };

    stage(0, 0); CP_COMMIT();
    for (int sl = 0; sl < 4; sl++) {
        if (sl < 3) { stage((sl + 1) & 1, sl + 1); CP_COMMIT(); CP_WAIT1(); }
        else        { CP_WAIT0(); }
        __syncthreads();
        uint32_t ab = sb + (sl & 1) * KV_BUF_A;
        uint32_t bb = sb + KV_B0 + (sl & 1) * KV_BUF_B;
#pragma unroll
        for (int k0 = 0; k0 < 32; k0 += 16) {
            uint32_t ah[4][4], al[4][4];
#pragma unroll
            for (int mt = 0; mt < 4; mt++) {
                uint32_t off = (uint32_t)(((k0 + lmod8 + 8 * l16) * 136 +
                                           wm * 64 + mt * 16 + 8 * l8) * 2);
                ldsm4t(ah[mt], ab + off);
                ldsm4t(al[mt], ab + 8704 + off);
            }
#pragma unroll
            for (int np = 0; np < 4; np++) {
                uint32_t bh2[4], bl2[4];
                uint32_t off = (uint32_t)(((k0 + lmod8 + 8 * l8) * 264 +
                                           wn * 64 + np * 16 + 8 * l16) * 2);
                ldsm4t(bh2, bb + off);
                ldsm4t(bl2, bb + 16896 + off);
#pragma unroll
                for (int mt = 0; mt < 4; mt++) {
                    mma_bf16(acc[mt][2*np],   ah[mt], bh2);
                    mma_bf16(acc[mt][2*np],   ah[mt], bl2);
                    mma_bf16(acc[mt][2*np],   al[mt], bh2);
                    mma_bf16(acc[mt][2*np+1], ah[mt], bh2 + 2);
                    mma_bf16(acc[mt][2*np+1], ah[mt], bl2 + 2);
                    mma_bf16(acc[mt][2*np+1], al[mt], bh2 + 2);
                }
            }
        }
        __syncthreads();
    }
    float* Sp = g_S + (size_t)(bh * NCH + ch) * (NN * NN);
#pragma unroll
    for (int mt = 0; mt < 4; mt++)
#pragma unroll
        for (int nt = 0; nt < 8; nt++)
#pragma unroll
            for (int h = 0; h < 2; h++) {
                int rr = m0g + wm * 64 + mt * 16 + lq + 8 * h;
                int cc = wn * 64 + nt * 8 + lr2;
                float2 o; o.x = acc[mt][nt][2*h]; o.y = acc[mt][nt][2*h+1];
                *(float2*)(Sp + (size_t)rr * NN + cc) = o;
            }
}

// ---------------- kernel 4: exclusive prefix scan + bf16 split (float4) ---------
__global__ void k_scan() {
    int g = blockIdx.x * blockDim.x + threadIdx.x;
    if (g >= BH * NN * NN / 4) return;
    int bh = g >> 14;
    int e4 = (g & 16383) << 2;
    size_t base = (size_t)bh * NCH * (NN * NN) + e4;
    float run0 = 0.f, run1 = 0.f, run2 = 0.f, run3 = 0.f;
#pragma unroll
    for (int i = 0; i < NCH; i++) {
        size_t p = base + (size_t)i * (NN * NN);
        float4 v = (i < NCH - 1) ? *(float4*)(g_S + p) : make_float4(0.f,0.f,0.f,0.f);
        __nv_bfloat16 h0 = __float2bfloat16(run0), h1 = __float2bfloat16(run1);
        __nv_bfloat16 h2 = __float2bfloat16(run2), h3 = __float2bfloat16(run3);
        __nv_bfloat162 H[2], L[2];
        H[0].x = h0; H[0].y = h1; H[1].x = h2; H[1].y = h3;
        L[0].x = __float2bfloat16(run0 - __bfloat162float(h0));
        L[0].y = __float2bfloat16(run1 - __bfloat162float(h1));
        L[1].x = __float2bfloat16(run2 - __bfloat162float(h2));
        L[1].y = __float2bfloat16(run3 - __bfloat162float(h3));
        *(uint2*)(g_Sh + p) = *(uint2*)H;
        *(uint2*)(g_Sl + p) = *(uint2*)L;
        run0 += v.x; run1 += v.y; run2 += v.z; run3 += v.w;
    }
}

// ---------------- kernel 5: Out = QR@S_pref + strict_tril(QR@KR^T)@V ------------
// double-buffered A (20480/buf) + B (33792/buf); P single-buffered.
#define AT_BUF_A 20480
#define AT_B0    40960
#define AT_BUF_B 33792
#define AT_PH    108544
#define AT_PL    143360
#define SMEM_ATTN 178176

__global__ void __launch_bounds__(256, 1) k_attn(float* __restrict__ out) {
    extern __shared__ char sm[];
    uint32_t sb = smem_u32(sm);
    int tid = threadIdx.x, lane = tid & 31, wid = tid >> 5;
    int wm = wid >> 2, wn = wid & 3;
    int bh = blockIdx.x >> 4, ch = blockIdx.x & 15;
    int t0 = ch * CC;
    int lm16 = lane & 15, l16 = lane >> 4, lmod8 = lane & 7, l8 = (lane >> 3) & 1;
    int lq = lane >> 2, lr2 = (lane & 3) * 2;

    const __nv_bfloat16* Qh = g_Qh + (size_t)(bh * TT + t0) * NN;
    const __nv_bfloat16* Ql = g_Ql + (size_t)(bh * TT + t0) * NN;
    const __nv_bfloat16* Kh = g_Kh + (size_t)(bh * TT + t0) * NN;
    const __nv_bfloat16* Kl = g_Kl + (size_t)(bh * TT + t0) * NN;
    const __nv_bfloat16* Vh = g_Vh + (size_t)(bh * TT + t0) * NN;
    const __nv_bfloat16* Vl = g_Vl + (size_t)(bh * TT + t0) * NN;
    const __nv_bfloat16* Sh = g_Sh + (size_t)(bh * NCH + ch) * (NN * NN);
    const __nv_bfloat16* Sl = g_Sl + (size_t)(bh * NCH + ch) * (NN * NN);

    // A slab loader: [128][40] hi+lo from (Q)
    auto stageQ = [&](int buf, int sl) {
        uint32_t ab = sb + buf * AT_BUF_A;
        int f0 = sl * 32;
        for (int v = tid; v < 512; v += 256) {
            int r = v >> 2, c8 = v & 3;
            uint32_t so = (uint32_t)(r * 80 + c8 * 16);
            cpa16(ab + so,         Qh + (size_t)r * NN + f0 + c8 * 8);
            cpa16(ab + 10240 + so, Ql + (size_t)r * NN + f0 + c8 * 8);
        }
    };
    // B slab loader (K-style, [128][40])
    auto stageK = [&](int buf, int sl) {
        uint32_t bb = sb + AT_B0 + buf * AT_BUF_B;
        int f0 = sl * 32;
        for (int v = tid; v < 512; v += 256) {
            int r = v >> 2, c8 = v & 3;
            uint32_t so = (uint32_t)(r * 80 + c8 * 16);
            cpa16(bb + so,         Kh + (size_t)r * NN + f0 + c8 * 8);
            cpa16(bb + 16896 + so, Kl + (size_t)r * NN + f0 + c8 * 8);
        }
    };
    // B slab loader (row-slab [32][264], from S or V)
    auto stageRS = [&](int buf, int sl, const __nv_bfloat16* pH, const __nv_bfloat16* pL) {
        uint32_t bb = sb + AT_B0 + buf * AT_BUF_B;
        int f0 = sl * 32;
        for (int v = tid; v < 1024; v += 256) {
            int r = v >> 5, c8 = v & 31;
            uint32_t so = (uint32_t)(r * 528 + c8 * 16);
            cpa16(bb + so,         pH + (size_t)(f0 + r) * NN + c8 * 8);
            cpa16(bb + 16896 + so, pL + (size_t)(f0 + r) * NN + c8 * 8);
        }
    };

    // ======== Stage 1: P = QR @ KR^T (warp tile 64x32) =========================
    {
        float acc1[4][4][4];
#pragma unroll
        for (int a = 0; a < 4; a++)
#pragma unroll
            for (int b = 0; b < 4; b++)
#pragma unroll
                for (int c = 0; c < 4; c++) acc1[a][b][c] = 0.f;

        stageQ(0, 0); stageK(0, 0); CP_COMMIT();
        for (int sl = 0; sl < 8; sl++) {
            if (sl < 7) { stageQ((sl+1)&1, sl+1); stageK((sl+1)&1, sl+1); CP_COMMIT(); CP_WAIT1(); }
            else        { CP_WAIT0(); }
            __syncthreads();
            uint32_t ab = sb + (sl & 1) * AT_BUF_A;
            uint32_t bb = sb + AT_B0 + (sl & 1) * AT_BUF_B;
#pragma unroll
            for (int k0 = 0; k0 < 32; k0 += 16) {
                uint32_t ah[4][4], al[4][4];
#pragma unroll
                for (int mt = 0; mt < 4; mt++) {
                    uint32_t off = (uint32_t)(((wm * 64 + mt * 16 + lm16) * 40 +
                                               k0 + 8 * l16) * 2);
                    ldsm4(ah[mt], ab + off);
                    ldsm4(al[mt], ab + 10240 + off);
                }
#pragma unroll
                for (int np = 0; np < 2; np++) {
                    uint32_t bh2[4], bl2[4];
                    uint32_t off = (uint32_t)(((wn * 32 + np * 16 + lmod8 + 8 * l16) * 40 +
                                               k0 + 8 * l8) * 2);
                    ldsm4(bh2, bb + off);
                    ldsm4(bl2, bb + 16896 + off);
#pragma unroll
                    for (int mt = 0; mt < 4; mt++) {
                        mma_bf16(acc1[mt][2*np],   ah[mt], bh2);
                        mma_bf16(acc1[mt][2*np],   ah[mt], bl2);
                        mma_bf16(acc1[mt][2*np],   al[mt], bh2);
                        mma_bf16(acc1[mt][2*np+1], ah[mt], bh2 + 2);
                        mma_bf16(acc1[mt][2*np+1], ah[mt], bl2 + 2);
                        mma_bf16(acc1[mt][2*np+1], al[mt], bh2 + 2);
                    }
                }
            }
            __syncthreads();
        }
        // mask + bf16 split into smem P
#pragma unroll
        for (int mt = 0; mt < 4; mt++)
#pragma unroll
            for (int nt = 0; nt < 4; nt++)
#pragma unroll
                for (int h = 0; h < 2; h++) {
                    int rr = wm * 64 + mt * 16 + lq + 8 * h;
                    int cn = wn * 32 + nt * 8 + lr2;
                    float v0 = (cn     < rr) ? acc1[mt][nt][2*h]   : 0.f;
                    float v1 = (cn + 1 < rr) ? acc1[mt][nt][2*h+1] : 0.f;
                    __nv_bfloat16 h0 = __float2bfloat16(v0);
                    __nv_bfloat16 h1 = __float2bfloat16(v1);
                    __nv_bfloat16 l0 = __float2bfloat16(v0 - __bfloat162float(h0));
                    __nv_bfloat16 l1 = __float2bfloat16(v1 - __bfloat162float(h1));
                    uint32_t bo = (uint32_t)((rr * 136 + cn) * 2);
                    __nv_bfloat162 ph2; ph2.x = h0; ph2.y = h1;
                    __nv_bfloat162 pl2; pl2.x = l0; pl2.y = l1;
                    *(__nv_bfloat162*)(sm + AT_PH + bo) = ph2;
                    *(__nv_bfloat162*)(sm + AT_PL + bo) = pl2;
                }
        __syncthreads();
    }

    // ======== Stages 2+3: D = QR@S_pref + P@V (warp tile 64x64) ================
    float acc[4][8][4];
#pragma unroll
    for (int a = 0; a < 4; a++)
#pragma unroll
        for (int b = 0; b < 8; b++)
#pragma unroll
            for (int c = 0; c < 4; c++) acc[a][b][c] = 0.f;

    if (ch > 0) {
        stageQ(0, 0); stageRS(0, 0, Sh, Sl); CP_COMMIT();
        for (int sl = 0; sl < 8; sl++) {
            if (sl < 7) { stageQ((sl+1)&1, sl+1); stageRS((sl+1)&1, sl+1, Sh, Sl); CP_COMMIT(); CP_WAIT1(); }
            else        { CP_WAIT0(); }
            __syncthreads();
            uint32_t ab = sb + (sl & 1) * AT_BUF_A;
            uint32_t bb = sb + AT_B0 + (sl & 1) * AT_BUF_B;
#pragma unroll
            for (int k0 = 0; k0 < 32; k0 += 16) {
                uint32_t ah[4][4], al[4][4];
#pragma unroll
                for (int mt = 0; mt < 4; mt++) {
                    uint32_t off = (uint32_t)(((wm * 64 + mt * 16 + lm16) * 40 +
                                               k0 + 8 * l16) * 2);
                    ldsm4(ah[mt], ab + off);
                    ldsm4(al[mt], ab + 10240 + off);
                }
#pragma unroll
                for (int np = 0; np < 4; np++) {
                    uint32_t bh2[4], bl2[4];
                    uint32_t off = (uint32_t)(((k0 + lmod8 + 8 * l8) * 264 +
                                               wn * 64 + np * 16 + 8 * l16) * 2);
                    ldsm4t(bh2, bb + off);
                    ldsm4t(bl2, bb + 16896 + off);
#pragma unroll
                    for (int mt = 0; mt < 4; mt++) {
                        mma_bf16(acc[mt][2*np],   ah[mt], bh2);
                        mma_bf16(acc[mt][2*np],   ah[mt], bl2);
                        mma_bf16(acc[mt][2*np],   al[mt], bh2);
                        mma_bf16(acc[mt][2*np+1], ah[mt], bh2 + 2);
                        mma_bf16(acc[mt][2*np+1], ah[mt], bl2 + 2);
                        mma_bf16(acc[mt][2*np+1], al[mt], bh2 + 2);
                    }
                }
            }
            __syncthreads();
        }
    }

    // Stage 3: D += P @ V (A = P in smem)
    stageRS(0, 0, Vh, Vl); CP_COMMIT();
    for (int sl = 0; sl < 4; sl++) {
        if (sl < 3) { stageRS((sl+1)&1, sl+1, Vh, Vl); CP_COMMIT(); CP_WAIT1(); }
        else        { CP_WAIT0(); }
        __syncthreads();
        int s0 = sl * 32;
        uint32_t bb = sb + AT_B0 + (sl & 1) * AT_BUF_B;
#pragma unroll
        for (int k0 = 0; k0 < 32; k0 += 16) {
            uint32_t ah[4][4], al[4][4];
#pragma unroll
            for (int mt = 0; mt < 4; mt++) {
                uint32_t off = (uint32_t)(((wm * 64 + mt * 16 + lm16) * 136 +
                                           s0 + k0 + 8 * l16) * 2);
                ldsm4(ah[mt], sb + AT_PH + off);
                ldsm4(al[mt], sb + AT_PL + off);
            }
#pragma unroll
            for (int np = 0; np < 4; np++) {
                uint32_t bh2[4], bl2[4];
                uint32_t off = (uint32_t)(((k0 + lmod8 + 8 * l8) * 264 +
                                           wn * 64 + np * 16 + 8 * l16) * 2);
                ldsm4t(bh2, bb + off);
                ldsm4t(bl2, bb + 16896 + off);
#pragma unroll
                for (int mt = 0; mt < 4; mt++) {
                    mma_bf16(acc[mt][2*np],   ah[mt], bh2);
                    mma_bf16(acc[mt][2*np],   ah[mt], bl2);
                    mma_bf16(acc[mt][2*np],   al[mt], bh2);
                    mma_bf16(acc[mt][2*np+1], ah[mt], bh2 + 2);
                    mma_bf16(acc[mt][2*np+1], ah[mt], bl2 + 2);
                    mma_bf16(acc[mt][2*np+1], al[mt], bh2 + 2);
                }
            }
        }
        __syncthreads();
    }

    // epilogue
#pragma unroll
    for (int mt = 0; mt < 4; mt++)
#pragma unroll
        for (int nt = 0; nt < 8; nt++)
#pragma unroll
            for (int h = 0; h < 2; h++) {
                int rr = wm * 64 + mt * 16 + lq + 8 * h;
                int cc = wn * 64 + nt * 8 + lr2;
                float2 o; o.x = acc[mt][nt][2*h]; o.y = acc[mt][nt][2*h+1];
                *(float2*)(out + (size_t)(bh * TT + t0 + rr) * NN + cc) = o;
            }
}

// ---------------- launcher -------------------------------------------------------
extern "C" void kernel_launch(void* const* d_in, const int* in_sizes, int n_in,
                              void* d_out, int out_size) {
    const float* Q = (const float*)d_in[0];
    const float* K = (const float*)d_in[1];
    const float* V = (const float*)d_in[2];
    float* out = (float*)d_out;

    static bool attr_set = false;
    if (!attr_set) {
        cudaFuncSetAttribute(k_kv,   cudaFuncAttributeMaxDynamicSharedMemorySize, SMEM_KV);
        cudaFuncSetAttribute(k_attn, cudaFuncAttributeMaxDynamicSharedMemorySize, SMEM_ATTN);
        attr_set = true;
    }

    k_tables<<<512, 512>>>();
    int prep_total = 3 * BH * TT * (NN / 4);
    k_prep<<<(prep_total + 255) / 256, 256>>>(Q, K, V);
    k_kv<<<dim3(BH * (NCH - 1), 2), 256, SMEM_KV>>>();
    k_scan<<<(BH * NN * NN / 4 + 255) / 256, 256>>>();
    k_attn<<<BH * NCH, 256, SMEM_ATTN>>>(out);
}

// round 6
// speedup vs baseline: 2.1521x; 1.0194x over previous
#include <cuda_runtime.h>
#include <cuda_bf16.h>
#include <math.h>
#include <stdint.h>

#define BH   24
#define TT   2048
#define NN   256
#define CC   128
#define NCH  16

// ---------------- device scratch ----------------------------------------------
__device__ float g_tabc[TT * (NN/2)];
__device__ float g_tabs[TT * (NN/2)];
__device__ __nv_bfloat16 g_Qh[BH*TT*NN], g_Ql[BH*TT*NN];
__device__ __nv_bfloat16 g_Kh[BH*TT*NN], g_Kl[BH*TT*NN];
__device__ __nv_bfloat16 g_Vh[BH*TT*NN], g_Vl[BH*TT*NN];
__device__ float g_S[BH*NCH*NN*NN];
__device__ __nv_bfloat16 g_Sh[BH*NCH*NN*NN], g_Sl[BH*NCH*NN*NN];

// ---------------- PTX helpers ---------------------------------------------------
__device__ __forceinline__ uint32_t smem_u32(const void* p) {
    uint32_t a;
    asm("{ .reg .u64 t; cvta.to.shared.u64 t, %1; cvt.u32.u64 %0, t; }" : "=r"(a) : "l"(p));
    return a;
}
__device__ __forceinline__ void cpa16(uint32_t s, const void* g) {
    asm volatile("cp.async.cg.shared.global [%0], [%1], 16;" :: "r"(s), "l"(g));
}
#define CP_COMMIT() asm volatile("cp.async.commit_group;" ::: "memory")
#define CP_WAIT0()  asm volatile("cp.async.wait_group 0;" ::: "memory")
#define CP_WAIT1()  asm volatile("cp.async.wait_group 1;" ::: "memory")

__device__ __forceinline__ void ldsm4(uint32_t* r, uint32_t a) {
    asm volatile("ldmatrix.sync.aligned.m8n8.x4.shared.b16 {%0,%1,%2,%3}, [%4];"
        : "=r"(r[0]), "=r"(r[1]), "=r"(r[2]), "=r"(r[3]) : "r"(a));
}
__device__ __forceinline__ void ldsm4t(uint32_t* r, uint32_t a) {
    asm volatile("ldmatrix.sync.aligned.m8n8.x4.trans.shared.b16 {%0,%1,%2,%3}, [%4];"
        : "=r"(r[0]), "=r"(r[1]), "=r"(r[2]), "=r"(r[3]) : "r"(a));
}
__device__ __forceinline__ void mma_bf16(float* d, const uint32_t* a, const uint32_t* b) {
    asm volatile("mma.sync.aligned.m16n8k16.row.col.f32.bf16.bf16.f32 "
        "{%0,%1,%2,%3}, {%4,%5,%6,%7}, {%8,%9}, {%0,%1,%2,%3};"
        : "+f"(d[0]), "+f"(d[1]), "+f"(d[2]), "+f"(d[3])
        : "r"(a[0]), "r"(a[1]), "r"(a[2]), "r"(a[3]), "r"(b[0]), "r"(b[1]));
}

// ---------------- kernel 1: RoPE phase tables -----------------------------------
__global__ void k_tables() {
    int id = blockIdx.x * blockDim.x + threadIdx.x;
    if (id >= TT * (NN/2)) return;
    int t = id >> 7;
    int j = id & 127;
    double fr_d = exp2(-(double)j / 8.0) / (2.0 * 3.14159265358979323846);
    float f32 = (float)fr_d;
    float ph  = (float)t * f32;
    ph = ph - floorf(ph);
    float ang = ph * 6.28318530717958647692f;
    double angd = (double)ang;
    g_tabc[id] = (float)cos(angd);
    g_tabs[id] = (float)sin(angd);
}

// ---------------- kernel 2: RoPE + bf16 hi/lo split (float4) --------------------
__global__ void k_prep(const float* __restrict__ Q, const float* __restrict__ K,
                       const float* __restrict__ V) {
    int idx = blockIdx.x * blockDim.x + threadIdx.x;
    const int per = BH * TT * (NN/4);
    if (idx >= 3 * per) return;
    int which = idx / per;
    int i = idx - which * per;
    int n4 = i & 63;
    int t  = (i >> 6) & 2047;
    int bh = i >> 17;
    int off = (bh * TT + t) * NN + 4 * n4;
    const float* src = (which == 0) ? Q : (which == 1) ? K : V;
    float4 v = *(const float4*)(src + off);
    float4 r;
    if (which < 2) {
        float c0 = g_tabc[t * 128 + 2*n4],     s0 = g_tabs[t * 128 + 2*n4];
        float c1 = g_tabc[t * 128 + 2*n4 + 1], s1 = g_tabs[t * 128 + 2*n4 + 1];
        r.x = v.x * c0 - v.y * s0;
        r.y = v.y * c0 + v.x * s0;
        r.z = v.z * c1 - v.w * s1;
        r.w = v.w * c1 + v.z * s1;
    } else r = v;
    __nv_bfloat16 h0 = __float2bfloat16(r.x), h1 = __float2bfloat16(r.y);
    __nv_bfloat16 h2 = __float2bfloat16(r.z), h3 = __float2bfloat16(r.w);
    __nv_bfloat16 l0 = __float2bfloat16(r.x - __bfloat162float(h0));
    __nv_bfloat16 l1 = __float2bfloat16(r.y - __bfloat162float(h1));
    __nv_bfloat16 l2 = __float2bfloat16(r.z - __bfloat162float(h2));
    __nv_bfloat16 l3 = __float2bfloat16(r.w - __bfloat162float(h3));
    __nv_bfloat16* dh = (which == 0) ? g_Qh : (which == 1) ? g_Kh : g_Vh;
    __nv_bfloat16* dl = (which == 0) ? g_Ql : (which == 1) ? g_Kl : g_Vl;
    __nv_bfloat162 H[2], L[2];
    H[0].x = h0; H[0].y = h1; H[1].x = h2; H[1].y = h3;
    L[0].x = l0; L[0].y = l1; L[1].x = l2; L[1].y = l3;
    *(uint2*)(dh + off) = *(uint2*)H;
    *(uint2*)(dl + off) = *(uint2*)L;
}

// ---------------- kernel 3: chunk KV state S_ch = KR^T @ V ----------------------
#define KV_BUF_A 17408
#define KV_BUF_B 33792
#define KV_B0    34816
#define SMEM_KV  102400

__global__ void __launch_bounds__(512, 1) k_kv() {
    extern __shared__ char sm[];
    uint32_t sb = smem_u32(sm);
    int tid = threadIdx.x, lane = tid & 31, wid = tid >> 5;
    int wm = wid >> 2, wn = wid & 3;           // 4x4 warp grid
    int bx = blockIdx.x;
    int bh = bx / 15, ch = bx % 15;
    int m0g = blockIdx.y * 128;
    int t0 = ch * CC;
    int l16 = lane >> 4, lmod8 = lane & 7, l8 = (lane >> 3) & 1;
    int lq = lane >> 2, lr2 = (lane & 3) * 2;

    const __nv_bfloat16* Kh = g_Kh + (size_t)(bh * TT + t0) * NN;
    const __nv_bfloat16* Kl = g_Kl + (size_t)(bh * TT + t0) * NN;
    const __nv_bfloat16* Vh = g_Vh + (size_t)(bh * TT + t0) * NN;
    const __nv_bfloat16* Vl = g_Vl + (size_t)(bh * TT + t0) * NN;

    float acc[2][8][4];
#pragma unroll
    for (int a = 0; a < 2; a++)
#pragma unroll
        for (int b = 0; b < 8; b++)
#pragma unroll
            for (int c = 0; c < 4; c++) acc[a][b][c] = 0.f;

    auto stage = [&](int buf, int sl) {
        uint32_t abase = sb + buf * KV_BUF_A;
        const __nv_bfloat16* gH = Kh + (size_t)sl * 32 * NN + m0g;
        const __nv_bfloat16* gL = Kl + (size_t)sl * 32 * NN + m0g;
        {   // 512 vec16 pairs, one per thread
            int r = tid >> 4, c8 = tid & 15;
            uint32_t so = (uint32_t)(r * 272 + c8 * 16);
            cpa16(abase + so,        gH + (size_t)r * NN + c8 * 8);
            cpa16(abase + 8704 + so, gL + (size_t)r * NN + c8 * 8);
        }
        uint32_t bbase = sb + KV_B0 + buf * KV_BUF_B;
        const __nv_bfloat16* vH = Vh + (size_t)sl * 32 * NN;
        const __nv_bfloat16* vL = Vl + (size_t)sl * 32 * NN;
#pragma unroll
        for (int v = tid; v < 1024; v += 512) {
            int r = v >> 5, c8 = v & 31;
            uint32_t so = (uint32_t)(r * 528 + c8 * 16);
            cpa16(bbase + so,         vH + (size_t)r * NN + c8 * 8);
            cpa16(bbase + 16896 + so, vL + (size_t)r * NN + c8 * 8);
        }
    };

    stage(0, 0); CP_COMMIT();
    for (int sl = 0; sl < 4; sl++) {
        if (sl < 3) { stage((sl + 1) & 1, sl + 1); CP_COMMIT(); CP_WAIT1(); }
        else        { CP_WAIT0(); }
        __syncthreads();
        uint32_t ab = sb + (sl & 1) * KV_BUF_A;
        uint32_t bb = sb + KV_B0 + (sl & 1) * KV_BUF_B;
#pragma unroll
        for (int k0 = 0; k0 < 32; k0 += 16) {
            uint32_t ah[2][4], al[2][4];
#pragma unroll
            for (int mt = 0; mt < 2; mt++) {
                uint32_t off = (uint32_t)(((k0 + lmod8 + 8 * l16) * 136 +
                                           wm * 32 + mt * 16 + 8 * l8) * 2);
                ldsm4t(ah[mt], ab + off);
                ldsm4t(al[mt], ab + 8704 + off);
            }
#pragma unroll
            for (int np = 0; np < 4; np++) {
                uint32_t bh2[4], bl2[4];
                uint32_t off = (uint32_t)(((k0 + lmod8 + 8 * l8) * 264 +
                                           wn * 64 + np * 16 + 8 * l16) * 2);
                ldsm4t(bh2, bb + off);
                ldsm4t(bl2, bb + 16896 + off);
#pragma unroll
                for (int mt = 0; mt < 2; mt++) {
                    mma_bf16(acc[mt][2*np],   ah[mt], bh2);
                    mma_bf16(acc[mt][2*np],   ah[mt], bl2);
                    mma_bf16(acc[mt][2*np],   al[mt], bh2);
                    mma_bf16(acc[mt][2*np+1], ah[mt], bh2 + 2);
                    mma_bf16(acc[mt][2*np+1], ah[mt], bl2 + 2);
                    mma_bf16(acc[mt][2*np+1], al[mt], bh2 + 2);
                }
            }
        }
        __syncthreads();
    }
    float* Sp = g_S + (size_t)(bh * NCH + ch) * (NN * NN);
#pragma unroll
    for (int mt = 0; mt < 2; mt++)
#pragma unroll
        for (int nt = 0; nt < 8; nt++)
#pragma unroll
            for (int h = 0; h < 2; h++) {
                int rr = m0g + wm * 32 + mt * 16 + lq + 8 * h;
                int cc = wn * 64 + nt * 8 + lr2;
                float2 o; o.x = acc[mt][nt][2*h]; o.y = acc[mt][nt][2*h+1];
                *(float2*)(Sp + (size_t)rr * NN + cc) = o;
            }
}

// ---------------- kernel 4: exclusive prefix scan + bf16 split (MLP) ------------
__global__ void k_scan() {
    int g = blockIdx.x * blockDim.x + threadIdx.x;
    if (g >= BH * NN * NN / 4) return;
    int bh = g >> 14;
    int e4 = (g & 16383) << 2;
    size_t base = (size_t)bh * NCH * (NN * NN) + e4;
    float4 vals[NCH - 1];
#pragma unroll
    for (int i = 0; i < NCH - 1; i++)
        vals[i] = *(const float4*)(g_S + base + (size_t)i * (NN * NN));
    float r0 = 0.f, r1 = 0.f, r2 = 0.f, r3 = 0.f;
#pragma unroll
    for (int i = 0; i < NCH; i++) {
        size_t p = base + (size_t)i * (NN * NN);
        __nv_bfloat16 h0 = __float2bfloat16(r0), h1 = __float2bfloat16(r1);
        __nv_bfloat16 h2 = __float2bfloat16(r2), h3 = __float2bfloat16(r3);
        __nv_bfloat162 H[2], L[2];
        H[0].x = h0; H[0].y = h1; H[1].x = h2; H[1].y = h3;
        L[0].x = __float2bfloat16(r0 - __bfloat162float(h0));
        L[0].y = __float2bfloat16(r1 - __bfloat162float(h1));
        L[1].x = __float2bfloat16(r2 - __bfloat162float(h2));
        L[1].y = __float2bfloat16(r3 - __bfloat162float(h3));
        *(uint2*)(g_Sh + p) = *(uint2*)H;
        *(uint2*)(g_Sl + p) = *(uint2*)L;
        if (i < NCH - 1) { r0 += vals[i].x; r1 += vals[i].y; r2 += vals[i].z; r3 += vals[i].w; }
    }
}

// ---------------- kernel 5: Out = QR@S_pref + strict_tril(QR@KR^T)@V ------------
#define AT_BUF_A 20480
#define AT_B0    40960
#define AT_BUF_B 33792
#define AT_PH    108544
#define AT_PL    143360
#define SMEM_ATTN 178176

__global__ void __launch_bounds__(512, 1) k_attn(float* __restrict__ out) {
    extern __shared__ char sm[];
    uint32_t sb = smem_u32(sm);
    int tid = threadIdx.x, lane = tid & 31, wid = tid >> 5;
    int wm = wid >> 2, wn = wid & 3;           // 4x4 warp grid
    int bh = blockIdx.x >> 4, ch = blockIdx.x & 15;
    int t0 = ch * CC;
    int lm16 = lane & 15, l16 = lane >> 4, lmod8 = lane & 7, l8 = (lane >> 3) & 1;
    int lq = lane >> 2, lr2 = (lane & 3) * 2;

    const __nv_bfloat16* Qh = g_Qh + (size_t)(bh * TT + t0) * NN;
    const __nv_bfloat16* Ql = g_Ql + (size_t)(bh * TT + t0) * NN;
    const __nv_bfloat16* Kh = g_Kh + (size_t)(bh * TT + t0) * NN;
    const __nv_bfloat16* Kl = g_Kl + (size_t)(bh * TT + t0) * NN;
    const __nv_bfloat16* Vh = g_Vh + (size_t)(bh * TT + t0) * NN;
    const __nv_bfloat16* Vl = g_Vl + (size_t)(bh * TT + t0) * NN;
    const __nv_bfloat16* Sh = g_Sh + (size_t)(bh * NCH + ch) * (NN * NN);
    const __nv_bfloat16* Sl = g_Sl + (size_t)(bh * NCH + ch) * (NN * NN);

    auto stageQ = [&](int buf, int sl) {
        uint32_t ab = sb + buf * AT_BUF_A;
        int f0 = sl * 32;
        int r = tid >> 2, c8 = tid & 3;
        uint32_t so = (uint32_t)(r * 80 + c8 * 16);
        cpa16(ab + so,         Qh + (size_t)r * NN + f0 + c8 * 8);
        cpa16(ab + 10240 + so, Ql + (size_t)r * NN + f0 + c8 * 8);
    };
    auto stageK = [&](int buf, int sl) {
        uint32_t bb = sb + AT_B0 + buf * AT_BUF_B;
        int f0 = sl * 32;
        int r = tid >> 2, c8 = tid & 3;
        uint32_t so = (uint32_t)(r * 80 + c8 * 16);
        cpa16(bb + so,         Kh + (size_t)r * NN + f0 + c8 * 8);
        cpa16(bb + 16896 + so, Kl + (size_t)r * NN + f0 + c8 * 8);
    };
    auto stageRS = [&](int buf, int sl, const __nv_bfloat16* pH, const __nv_bfloat16* pL) {
        uint32_t bb = sb + AT_B0 + buf * AT_BUF_B;
        int f0 = sl * 32;
#pragma unroll
        for (int v = tid; v < 1024; v += 512) {
            int r = v >> 5, c8 = v & 31;
            uint32_t so = (uint32_t)(r * 528 + c8 * 16);
            cpa16(bb + so,         pH + (size_t)(f0 + r) * NN + c8 * 8);
            cpa16(bb + 16896 + so, pL + (size_t)(f0 + r) * NN + c8 * 8);
        }
    };

    // ======== Stage 1: P = QR @ KR^T (warp tile 32x32) =========================
    {
        float acc1[2][4][4];
#pragma unroll
        for (int a = 0; a < 2; a++)
#pragma unroll
            for (int b = 0; b < 4; b++)
#pragma unroll
                for (int c = 0; c < 4; c++) acc1[a][b][c] = 0.f;

        stageQ(0, 0); stageK(0, 0); CP_COMMIT();
        for (int sl = 0; sl < 8; sl++) {
            if (sl < 7) {
                stageQ((sl+1)&1, sl+1); stageK((sl+1)&1, sl+1);
            } else {
                // prefetch next stage's first slab into buf 0
                if (ch > 0) { stageQ(0, 0); stageRS(0, 0, Sh, Sl); }
                else        { stageRS(0, 0, Vh, Vl); }
            }
            CP_COMMIT(); CP_WAIT1();
            __syncthreads();
            uint32_t ab = sb + (sl & 1) * AT_BUF_A;
            uint32_t bb = sb + AT_B0 + (sl & 1) * AT_BUF_B;
#pragma unroll
            for (int k0 = 0; k0 < 32; k0 += 16) {
                uint32_t ah[2][4], al[2][4];
#pragma unroll
                for (int mt = 0; mt < 2; mt++) {
                    uint32_t off = (uint32_t)(((wm * 32 + mt * 16 + lm16) * 40 +
                                               k0 + 8 * l16) * 2);
                    ldsm4(ah[mt], ab + off);
                    ldsm4(al[mt], ab + 10240 + off);
                }
#pragma unroll
                for (int np = 0; np < 2; np++) {
                    uint32_t bh2[4], bl2[4];
                    uint32_t off = (uint32_t)(((wn * 32 + np * 16 + lmod8 + 8 * l16) * 40 +
                                               k0 + 8 * l8) * 2);
                    ldsm4(bh2, bb + off);
                    ldsm4(bl2, bb + 16896 + off);
#pragma unroll
                    for (int mt = 0; mt < 2; mt++) {
                        mma_bf16(acc1[mt][2*np],   ah[mt], bh2);
                        mma_bf16(acc1[mt][2*np],   ah[mt], bl2);
                        mma_bf16(acc1[mt][2*np],   al[mt], bh2);
                        mma_bf16(acc1[mt][2*np+1], ah[mt], bh2 + 2);
                        mma_bf16(acc1[mt][2*np+1], ah[mt], bl2 + 2);
                        mma_bf16(acc1[mt][2*np+1], al[mt], bh2 + 2);
                    }
                }
            }
            __syncthreads();
        }
        // mask (strict lower triangle) + bf16 split into smem P
#pragma unroll
        for (int mt = 0; mt < 2; mt++)
#pragma unroll
            for (int nt = 0; nt < 4; nt++)
#pragma unroll
                for (int h = 0; h < 2; h++) {
                    int rr = wm * 32 + mt * 16 + lq + 8 * h;
                    int cn = wn * 32 + nt * 8 + lr2;
                    float v0 = (cn     < rr) ? acc1[mt][nt][2*h]   : 0.f;
                    float v1 = (cn + 1 < rr) ? acc1[mt][nt][2*h+1] : 0.f;
                    __nv_bfloat16 h0 = __float2bfloat16(v0);
                    __nv_bfloat16 h1 = __float2bfloat16(v1);
                    __nv_bfloat16 l0 = __float2bfloat16(v0 - __bfloat162float(h0));
                    __nv_bfloat16 l1 = __float2bfloat16(v1 - __bfloat162float(h1));
                    uint32_t bo = (uint32_t)((rr * 136 + cn) * 2);
                    __nv_bfloat162 ph2; ph2.x = h0; ph2.y = h1;
                    __nv_bfloat162 pl2; pl2.x = l0; pl2.y = l1;
                    *(__nv_bfloat162*)(sm + AT_PH + bo) = ph2;
                    *(__nv_bfloat162*)(sm + AT_PL + bo) = pl2;
                }
        __syncthreads();
    }

    // ======== Stages 2+3: D = QR@S_pref + P@V (warp tile 32x64) ================
    float acc[2][8][4];
#pragma unroll
    for (int a = 0; a < 2; a++)
#pragma unroll
        for (int b = 0; b < 8; b++)
#pragma unroll
            for (int c = 0; c < 4; c++) acc[a][b][c] = 0.f;

    if (ch > 0) {
        for (int sl = 0; sl < 8; sl++) {
            if (sl < 7) { stageQ((sl+1)&1, sl+1); stageRS((sl+1)&1, sl+1, Sh, Sl); }
            else        { stageRS(0, 0, Vh, Vl); }   // prefetch stage-3 first V slab
            CP_COMMIT(); CP_WAIT1();
            __syncthreads();
            uint32_t ab = sb + (sl & 1) * AT_BUF_A;
            uint32_t bb = sb + AT_B0 + (sl & 1) * AT_BUF_B;
#pragma unroll
            for (int k0 = 0; k0 < 32; k0 += 16) {
                uint32_t ah[2][4], al[2][4];
#pragma unroll
                for (int mt = 0; mt < 2; mt++) {
                    uint32_t off = (uint32_t)(((wm * 32 + mt * 16 + lm16) * 40 +
                                               k0 + 8 * l16) * 2);
                    ldsm4(ah[mt], ab + off);
                    ldsm4(al[mt], ab + 10240 + off);
                }
#pragma unroll
                for (int np = 0; np < 4; np++) {
                    uint32_t bh2[4], bl2[4];
                    uint32_t off = (uint32_t)(((k0 + lmod8 + 8 * l8) * 264 +
                                               wn * 64 + np * 16 + 8 * l16) * 2);
                    ldsm4t(bh2, bb + off);
                    ldsm4t(bl2, bb + 16896 + off);
#pragma unroll
                    for (int mt = 0; mt < 2; mt++) {
                        mma_bf16(acc[mt][2*np],   ah[mt], bh2);
                        mma_bf16(acc[mt][2*np],   ah[mt], bl2);
                        mma_bf16(acc[mt][2*np],   al[mt], bh2);
                        mma_bf16(acc[mt][2*np+1], ah[mt], bh2 + 2);
                        mma_bf16(acc[mt][2*np+1], ah[mt], bl2 + 2);
                        mma_bf16(acc[mt][2*np+1], al[mt], bh2 + 2);
                    }
                }
            }
            __syncthreads();
        }
    }

    // Stage 3: D += P @ V (A = P in smem; first V slab already prefetched)
    for (int sl = 0; sl < 4; sl++) {
        if (sl < 3) { stageRS((sl+1)&1, sl+1, Vh, Vl); CP_COMMIT(); CP_WAIT1(); }
        else        { CP_WAIT0(); }
        __syncthreads();
        int s0 = sl * 32;
        uint32_t bb = sb + AT_B0 + (sl & 1) * AT_BUF_B;
#pragma unroll
        for (int k0 = 0; k0 < 32; k0 += 16) {
            uint32_t ah[2][4], al[2][4];
#pragma unroll
            for (int mt = 0; mt < 2; mt++) {
                uint32_t off = (uint32_t)(((wm * 32 + mt * 16 + lm16) * 136 +
                                           s0 + k0 + 8 * l16) * 2);
                ldsm4(ah[mt], sb + AT_PH + off);
                ldsm4(al[mt], sb + AT_PL + off);
            }
#pragma unroll
            for (int np = 0; np < 4; np++) {
                uint32_t bh2[4], bl2[4];
                uint32_t off = (uint32_t)(((k0 + lmod8 + 8 * l8) * 264 +
                                           wn * 64 + np * 16 + 8 * l16) * 2);
                ldsm4t(bh2, bb + off);
                ldsm4t(bl2, bb + 16896 + off);
#pragma unroll
                for (int mt = 0; mt < 2; mt++) {
                    mma_bf16(acc[mt][2*np],   ah[mt], bh2);
                    mma_bf16(acc[mt][2*np],   ah[mt], bl2);
                    mma_bf16(acc[mt][2*np],   al[mt], bh2);
                    mma_bf16(acc[mt][2*np+1], ah[mt], bh2 + 2);
                    mma_bf16(acc[mt][2*np+1], ah[mt], bl2 + 2);
                    mma_bf16(acc[mt][2*np+1], al[mt], bh2 + 2);
                }
            }
        }
        __syncthreads();
    }

    // epilogue
#pragma unroll
    for (int mt = 0; mt < 2; mt++)
#pragma unroll
        for (int nt = 0; nt < 8; nt++)
#pragma unroll
            for (int h = 0; h < 2; h++) {
                int rr = wm * 32 + mt * 16 + lq + 8 * h;
                int cc = wn * 64 + nt * 8 + lr2;
                float2 o; o.x = acc[mt][nt][2*h]; o.y = acc[mt][nt][2*h+1];
                *(float2*)(out + (size_t)(bh * TT + t0 + rr) * NN + cc) = o;
            }
}

// ---------------- launcher -------------------------------------------------------
extern "C" void kernel_launch(void* const* d_in, const int* in_sizes, int n_in,
                              void* d_out, int out_size) {
    const float* Q = (const float*)d_in[0];
    const float* K = (const float*)d_in[1];
    const float* V = (const float*)d_in[2];
    float* out = (float*)d_out;

    static bool attr_set = false;
    if (!attr_set) {
        cudaFuncSetAttribute(k_kv,   cudaFuncAttributeMaxDynamicSharedMemorySize, SMEM_KV);
        cudaFuncSetAttribute(k_attn, cudaFuncAttributeMaxDynamicSharedMemorySize, SMEM_ATTN);
        attr_set = true;
    }

    k_tables<<<512, 512>>>();
    int prep_total = 3 * BH * TT * (NN / 4);
    k_prep<<<(prep_total + 255) / 256, 256>>>(Q, K, V);
    k_kv<<<dim3(BH * (NCH - 1), 2), 512, SMEM_KV>>>();
    k_scan<<<(BH * NN * NN / 4 + 255) / 256, 256>>>();
    k_attn<<<BH * NCH, 512, SMEM_ATTN>>>(out);
}

// round 7
// speedup vs baseline: 2.2386x; 1.0402x over previous
#include <cuda_runtime.h>
#include <cuda_bf16.h>
#include <math.h>
#include <stdint.h>

#define BH   24
#define TT   2048
#define NN   256
#define CC   128
#define NCH  16

// ---------------- device scratch ----------------------------------------------
__device__ float g_tabc[TT * (NN/2)];
__device__ float g_tabs[TT * (NN/2)];
__device__ __nv_bfloat16 g_Qh[BH*TT*NN], g_Ql[BH*TT*NN];
__device__ __nv_bfloat16 g_Kh[BH*TT*NN], g_Kl[BH*TT*NN];
__device__ __nv_bfloat16 g_Vh[BH*TT*NN], g_Vl[BH*TT*NN];
__device__ float g_S[BH*NCH*NN*NN];
__device__ __nv_bfloat16 g_Sh[BH*NCH*NN*NN], g_Sl[BH*NCH*NN*NN];

// ---------------- PTX helpers ---------------------------------------------------
__device__ __forceinline__ uint32_t smem_u32(const void* p) {
    uint32_t a;
    asm("{ .reg .u64 t; cvta.to.shared.u64 t, %1; cvt.u32.u64 %0, t; }" : "=r"(a) : "l"(p));
    return a;
}
__device__ __forceinline__ void cpa16(uint32_t s, const void* g) {
    asm volatile("cp.async.cg.shared.global [%0], [%1], 16;" :: "r"(s), "l"(g));
}
#define CP_COMMIT() asm volatile("cp.async.commit_group;" ::: "memory")
#define CP_WAIT0()  asm volatile("cp.async.wait_group 0;" ::: "memory")
#define CP_WAIT1()  asm volatile("cp.async.wait_group 1;" ::: "memory")

__device__ __forceinline__ void ldsm4(uint32_t* r, uint32_t a) {
    asm volatile("ldmatrix.sync.aligned.m8n8.x4.shared.b16 {%0,%1,%2,%3}, [%4];"
        : "=r"(r[0]), "=r"(r[1]), "=r"(r[2]), "=r"(r[3]) : "r"(a));
}
__device__ __forceinline__ void ldsm4t(uint32_t* r, uint32_t a) {
    asm volatile("ldmatrix.sync.aligned.m8n8.x4.trans.shared.b16 {%0,%1,%2,%3}, [%4];"
        : "=r"(r[0]), "=r"(r[1]), "=r"(r[2]), "=r"(r[3]) : "r"(a));
}
__device__ __forceinline__ void mma_bf16(float* d, const uint32_t* a, const uint32_t* b) {
    asm volatile("mma.sync.aligned.m16n8k16.row.col.f32.bf16.bf16.f32 "
        "{%0,%1,%2,%3}, {%4,%5,%6,%7}, {%8,%9}, {%0,%1,%2,%3};"
        : "+f"(d[0]), "+f"(d[1]), "+f"(d[2]), "+f"(d[3])
        : "r"(a[0]), "r"(a[1]), "r"(a[2]), "r"(a[3]), "r"(b[0]), "r"(b[1]));
}

// ---------------- kernel 1: RoPE phase tables -----------------------------------
__global__ void k_tables() {
    int id = blockIdx.x * blockDim.x + threadIdx.x;
    if (id >= TT * (NN/2)) return;
    int t = id >> 7;
    int j = id & 127;
    double fr_d = exp2(-(double)j / 8.0) / (2.0 * 3.14159265358979323846);
    float f32 = (float)fr_d;
    float ph  = (float)t * f32;
    ph = ph - floorf(ph);
    float ang = ph * 6.28318530717958647692f;
    double angd = (double)ang;
    g_tabc[id] = (float)cos(angd);
    g_tabs[id] = (float)sin(angd);
}

// ---------------- kernel 2: RoPE + bf16 hi/lo split (float4) --------------------
__global__ void k_prep(const float* __restrict__ Q, const float* __restrict__ K,
                       const float* __restrict__ V) {
    int idx = blockIdx.x * blockDim.x + threadIdx.x;
    const int per = BH * TT * (NN/4);
    if (idx >= 3 * per) return;
    int which = idx / per;
    int i = idx - which * per;
    int n4 = i & 63;
    int t  = (i >> 6) & 2047;
    int bh = i >> 17;
    int off = (bh * TT + t) * NN + 4 * n4;
    const float* src = (which == 0) ? Q : (which == 1) ? K : V;
    float4 v = *(const float4*)(src + off);
    float4 r;
    if (which < 2) {
        float c0 = g_tabc[t * 128 + 2*n4],     s0 = g_tabs[t * 128 + 2*n4];
        float c1 = g_tabc[t * 128 + 2*n4 + 1], s1 = g_tabs[t * 128 + 2*n4 + 1];
        r.x = v.x * c0 - v.y * s0;
        r.y = v.y * c0 + v.x * s0;
        r.z = v.z * c1 - v.w * s1;
        r.w = v.w * c1 + v.z * s1;
    } else r = v;
    __nv_bfloat16 h0 = __float2bfloat16(r.x), h1 = __float2bfloat16(r.y);
    __nv_bfloat16 h2 = __float2bfloat16(r.z), h3 = __float2bfloat16(r.w);
    __nv_bfloat16 l0 = __float2bfloat16(r.x - __bfloat162float(h0));
    __nv_bfloat16 l1 = __float2bfloat16(r.y - __bfloat162float(h1));
    __nv_bfloat16 l2 = __float2bfloat16(r.z - __bfloat162float(h2));
    __nv_bfloat16 l3 = __float2bfloat16(r.w - __bfloat162float(h3));
    __nv_bfloat16* dh = (which == 0) ? g_Qh : (which == 1) ? g_Kh : g_Vh;
    __nv_bfloat16* dl = (which == 0) ? g_Ql : (which == 1) ? g_Kl : g_Vl;
    __nv_bfloat162 H[2], L[2];
    H[0].x = h0; H[0].y = h1; H[1].x = h2; H[1].y = h3;
    L[0].x = l0; L[0].y = l1; L[1].x = l2; L[1].y = l3;
    *(uint2*)(dh + off) = *(uint2*)H;
    *(uint2*)(dl + off) = *(uint2*)L;
}

// ---------------- kernel 3: chunk KV state S_ch = KR^T @ V ----------------------
#define KV_BUF_A 17408
#define KV_BUF_B 33792
#define KV_B0    34816
#define SMEM_KV  102400

__global__ void __launch_bounds__(512, 1) k_kv() {
    extern __shared__ char sm[];
    uint32_t sb = smem_u32(sm);
    int tid = threadIdx.x, lane = tid & 31, wid = tid >> 5;
    int wm = wid >> 2, wn = wid & 3;           // 4x4 warp grid
    int bx = blockIdx.x;
    int bh = bx / 15, ch = bx % 15;
    int m0g = blockIdx.y * 128;
    int t0 = ch * CC;
    int l16 = lane >> 4, lmod8 = lane & 7, l8 = (lane >> 3) & 1;
    int lq = lane >> 2, lr2 = (lane & 3) * 2;

    const __nv_bfloat16* Kh = g_Kh + (size_t)(bh * TT + t0) * NN;
    const __nv_bfloat16* Kl = g_Kl + (size_t)(bh * TT + t0) * NN;
    const __nv_bfloat16* Vh = g_Vh + (size_t)(bh * TT + t0) * NN;
    const __nv_bfloat16* Vl = g_Vl + (size_t)(bh * TT + t0) * NN;

    float acc[2][8][4];
#pragma unroll
    for (int a = 0; a < 2; a++)
#pragma unroll
        for (int b = 0; b < 8; b++)
#pragma unroll
            for (int c = 0; c < 4; c++) acc[a][b][c] = 0.f;

    auto stage = [&](int buf, int sl) {
        uint32_t abase = sb + buf * KV_BUF_A;
        const __nv_bfloat16* gH = Kh + (size_t)sl * 32 * NN + m0g;
        const __nv_bfloat16* gL = Kl + (size_t)sl * 32 * NN + m0g;
        {
            int r = tid >> 4, c8 = tid & 15;
            uint32_t so = (uint32_t)(r * 272 + c8 * 16);
            cpa16(abase + so,        gH + (size_t)r * NN + c8 * 8);
            cpa16(abase + 8704 + so, gL + (size_t)r * NN + c8 * 8);
        }
        uint32_t bbase = sb + KV_B0 + buf * KV_BUF_B;
        const __nv_bfloat16* vH = Vh + (size_t)sl * 32 * NN;
        const __nv_bfloat16* vL = Vl + (size_t)sl * 32 * NN;
#pragma unroll
        for (int v = tid; v < 1024; v += 512) {
            int r = v >> 5, c8 = v & 31;
            uint32_t so = (uint32_t)(r * 528 + c8 * 16);
            cpa16(bbase + so,         vH + (size_t)r * NN + c8 * 8);
            cpa16(bbase + 16896 + so, vL + (size_t)r * NN + c8 * 8);
        }
    };

    stage(0, 0); CP_COMMIT();
    for (int sl = 0; sl < 4; sl++) {
        if (sl < 3) { stage((sl + 1) & 1, sl + 1); CP_COMMIT(); CP_WAIT1(); }
        else        { CP_WAIT0(); }
        __syncthreads();
        uint32_t ab = sb + (sl & 1) * KV_BUF_A;
        uint32_t bb = sb + KV_B0 + (sl & 1) * KV_BUF_B;
#pragma unroll
        for (int k0 = 0; k0 < 32; k0 += 16) {
            uint32_t ah[2][4], al[2][4];
#pragma unroll
            for (int mt = 0; mt < 2; mt++) {
                uint32_t off = (uint32_t)(((k0 + lmod8 + 8 * l16) * 136 +
                                           wm * 32 + mt * 16 + 8 * l8) * 2);
                ldsm4t(ah[mt], ab + off);
                ldsm4t(al[mt], ab + 8704 + off);
            }
#pragma unroll
            for (int np = 0; np < 4; np++) {
                uint32_t bh2[4], bl2[4];
                uint32_t off = (uint32_t)(((k0 + lmod8 + 8 * l8) * 264 +
                                           wn * 64 + np * 16 + 8 * l16) * 2);
                ldsm4t(bh2, bb + off);
                ldsm4t(bl2, bb + 16896 + off);
#pragma unroll
                for (int mt = 0; mt < 2; mt++) {
                    mma_bf16(acc[mt][2*np],   ah[mt], bh2);
                    mma_bf16(acc[mt][2*np],   ah[mt], bl2);
                    mma_bf16(acc[mt][2*np],   al[mt], bh2);
                    mma_bf16(acc[mt][2*np+1], ah[mt], bh2 + 2);
                    mma_bf16(acc[mt][2*np+1], ah[mt], bl2 + 2);
                    mma_bf16(acc[mt][2*np+1], al[mt], bh2 + 2);
                }
            }
        }
        __syncthreads();
    }
    float* Sp = g_S + (size_t)(bh * NCH + ch) * (NN * NN);
#pragma unroll
    for (int mt = 0; mt < 2; mt++)
#pragma unroll
        for (int nt = 0; nt < 8; nt++)
#pragma unroll
            for (int h = 0; h < 2; h++) {
                int rr = m0g + wm * 32 + mt * 16 + lq + 8 * h;
                int cc = wn * 64 + nt * 8 + lr2;
                float2 o; o.x = acc[mt][nt][2*h]; o.y = acc[mt][nt][2*h+1];
                *(float2*)(Sp + (size_t)rr * NN + cc) = o;
            }
}

// ---------------- kernel 4: exclusive prefix scan + bf16 split (MLP) ------------
__global__ void k_scan() {
    int g = blockIdx.x * blockDim.x + threadIdx.x;
    if (g >= BH * NN * NN / 4) return;
    int bh = g >> 14;
    int e4 = (g & 16383) << 2;
    size_t base = (size_t)bh * NCH * (NN * NN) + e4;
    float4 vals[NCH - 1];
#pragma unroll
    for (int i = 0; i < NCH - 1; i++)
        vals[i] = *(const float4*)(g_S + base + (size_t)i * (NN * NN));
    float r0 = 0.f, r1 = 0.f, r2 = 0.f, r3 = 0.f;
#pragma unroll
    for (int i = 0; i < NCH; i++) {
        size_t p = base + (size_t)i * (NN * NN);
        __nv_bfloat16 h0 = __float2bfloat16(r0), h1 = __float2bfloat16(r1);
        __nv_bfloat16 h2 = __float2bfloat16(r2), h3 = __float2bfloat16(r3);
        __nv_bfloat162 H[2], L[2];
        H[0].x = h0; H[0].y = h1; H[1].x = h2; H[1].y = h3;
        L[0].x = __float2bfloat16(r0 - __bfloat162float(h0));
        L[0].y = __float2bfloat16(r1 - __bfloat162float(h1));
        L[1].x = __float2bfloat16(r2 - __bfloat162float(h2));
        L[1].y = __float2bfloat16(r3 - __bfloat162float(h3));
        *(uint2*)(g_Sh + p) = *(uint2*)H;
        *(uint2*)(g_Sl + p) = *(uint2*)L;
        if (i < NCH - 1) { r0 += vals[i].x; r1 += vals[i].y; r2 += vals[i].z; r3 += vals[i].w; }
    }
}

// ---------------- kernel 5: Out = QR@S_pref + strict_tril(QR@KR^T)@V ------------
#define AT_BUF_A 20480
#define AT_B0    40960
#define AT_BUF_B 33792
#define AT_PH    108544
#define AT_PL    143360
#define SMEM_ATTN 178176

// stage-1 warp->tile LUT (10 live lower-triangle tiles, 3/3/2/2 per SMSP)
#define S1_R_PACK 981476u   // r[wid] in bits [2*wid, 2*wid+1], wid<10
#define S1_C_PACK 54436u

__global__ void __launch_bounds__(512, 1) k_attn(float* __restrict__ out) {
    extern __shared__ char sm[];
    uint32_t sb = smem_u32(sm);
    int tid = threadIdx.x, lane = tid & 31, wid = tid >> 5;
    int wm = wid >> 2, wn = wid & 3;           // 4x4 warp grid (stages 2,3)
    int bh = blockIdx.x >> 4, ch = 15 - (blockIdx.x & 15);   // heavy chunks first
    int t0 = ch * CC;
    int lm16 = lane & 15, l16 = lane >> 4, lmod8 = lane & 7, l8 = (lane >> 3) & 1;
    int lq = lane >> 2, lr2 = (lane & 3) * 2;

    const __nv_bfloat16* Qh = g_Qh + (size_t)(bh * TT + t0) * NN;
    const __nv_bfloat16* Ql = g_Ql + (size_t)(bh * TT + t0) * NN;
    const __nv_bfloat16* Kh = g_Kh + (size_t)(bh * TT + t0) * NN;
    const __nv_bfloat16* Kl = g_Kl + (size_t)(bh * TT + t0) * NN;
    const __nv_bfloat16* Vh = g_Vh + (size_t)(bh * TT + t0) * NN;
    const __nv_bfloat16* Vl = g_Vl + (size_t)(bh * TT + t0) * NN;
    const __nv_bfloat16* Sh = g_Sh + (size_t)(bh * NCH + ch) * (NN * NN);
    const __nv_bfloat16* Sl = g_Sl + (size_t)(bh * NCH + ch) * (NN * NN);

    auto stageQ = [&](int buf, int sl) {
        uint32_t ab = sb + buf * AT_BUF_A;
        int f0 = sl * 32;
        int r = tid >> 2, c8 = tid & 3;
        uint32_t so = (uint32_t)(r * 80 + c8 * 16);
        cpa16(ab + so,         Qh + (size_t)r * NN + f0 + c8 * 8);
        cpa16(ab + 10240 + so, Ql + (size_t)r * NN + f0 + c8 * 8);
    };
    auto stageK = [&](int buf, int sl) {
        uint32_t bb = sb + AT_B0 + buf * AT_BUF_B;
        int f0 = sl * 32;
        int r = tid >> 2, c8 = tid & 3;
        uint32_t so = (uint32_t)(r * 80 + c8 * 16);
        cpa16(bb + so,         Kh + (size_t)r * NN + f0 + c8 * 8);
        cpa16(bb + 16896 + so, Kl + (size_t)r * NN + f0 + c8 * 8);
    };
    auto stageRS = [&](int buf, int sl, const __nv_bfloat16* pH, const __nv_bfloat16* pL) {
        uint32_t bb = sb + AT_B0 + buf * AT_BUF_B;
        int f0 = sl * 32;
#pragma unroll
        for (int v = tid; v < 1024; v += 512) {
            int r = v >> 5, c8 = v & 31;
            uint32_t so = (uint32_t)(r * 528 + c8 * 16);
            cpa16(bb + so,         pH + (size_t)(f0 + r) * NN + c8 * 8);
            cpa16(bb + 16896 + so, pL + (size_t)(f0 + r) * NN + c8 * 8);
        }
    };

    // ======== Stage 1: P = QR @ KR^T, lower-triangle tiles only ================
    {
        int pr = (S1_R_PACK >> (wid * 2)) & 3;
        int pc = (S1_C_PACK >> (wid * 2)) & 3;
        bool act1 = (wid < 10);

        float acc1[2][4][4];
#pragma unroll
        for (int a = 0; a < 2; a++)
#pragma unroll
            for (int b = 0; b < 4; b++)
#pragma unroll
                for (int c = 0; c < 4; c++) acc1[a][b][c] = 0.f;

        stageQ(0, 0); stageK(0, 0); CP_COMMIT();
        for (int sl = 0; sl < 8; sl++) {
            if (sl < 7) {
                stageQ((sl+1)&1, sl+1); stageK((sl+1)&1, sl+1);
            } else {
                if (ch > 0) { stageQ(0, 0); stageRS(0, 0, Sh, Sl); }
                else        { stageRS(0, 0, Vh, Vl); }
            }
            CP_COMMIT(); CP_WAIT1();
            __syncthreads();
            if (act1) {
                uint32_t ab = sb + (sl & 1) * AT_BUF_A;
                uint32_t bb = sb + AT_B0 + (sl & 1) * AT_BUF_B;
#pragma unroll
                for (int k0 = 0; k0 < 32; k0 += 16) {
                    uint32_t ah[2][4], al[2][4];
#pragma unroll
                    for (int mt = 0; mt < 2; mt++) {
                        uint32_t off = (uint32_t)(((pr * 32 + mt * 16 + lm16) * 40 +
                                                   k0 + 8 * l16) * 2);
                        ldsm4(ah[mt], ab + off);
                        ldsm4(al[mt], ab + 10240 + off);
                    }
#pragma unroll
                    for (int np = 0; np < 2; np++) {
                        uint32_t bh2[4], bl2[4];
                        uint32_t off = (uint32_t)(((pc * 32 + np * 16 + lmod8 + 8 * l16) * 40 +
                                                   k0 + 8 * l8) * 2);
                        ldsm4(bh2, bb + off);
                        ldsm4(bl2, bb + 16896 + off);
#pragma unroll
                        for (int mt = 0; mt < 2; mt++) {
                            mma_bf16(acc1[mt][2*np],   ah[mt], bh2);
                            mma_bf16(acc1[mt][2*np],   ah[mt], bl2);
                            mma_bf16(acc1[mt][2*np],   al[mt], bh2);
                            mma_bf16(acc1[mt][2*np+1], ah[mt], bh2 + 2);
                            mma_bf16(acc1[mt][2*np+1], ah[mt], bl2 + 2);
                            mma_bf16(acc1[mt][2*np+1], al[mt], bh2 + 2);
                        }
                    }
                }
            }
            __syncthreads();
        }
        // mask (strict lower triangle) + bf16 split into smem P (live tiles only)
        if (act1) {
#pragma unroll
            for (int mt = 0; mt < 2; mt++)
#pragma unroll
                for (int nt = 0; nt < 4; nt++)
#pragma unroll
                    for (int h = 0; h < 2; h++) {
                        int rr = pr * 32 + mt * 16 + lq + 8 * h;
                        int cn = pc * 32 + nt * 8 + lr2;
                        float v0 = (cn     < rr) ? acc1[mt][nt][2*h]   : 0.f;
                        float v1 = (cn + 1 < rr) ? acc1[mt][nt][2*h+1] : 0.f;
                        __nv_bfloat16 h0 = __float2bfloat16(v0);
                        __nv_bfloat16 h1 = __float2bfloat16(v1);
                        __nv_bfloat16 l0 = __float2bfloat16(v0 - __bfloat162float(h0));
                        __nv_bfloat16 l1 = __float2bfloat16(v1 - __bfloat162float(h1));
                        uint32_t bo = (uint32_t)((rr * 136 + cn) * 2);
                        __nv_bfloat162 ph2; ph2.x = h0; ph2.y = h1;
                        __nv_bfloat162 pl2; pl2.x = l0; pl2.y = l1;
                        *(__nv_bfloat162*)(sm + AT_PH + bo) = ph2;
                        *(__nv_bfloat162*)(sm + AT_PL + bo) = pl2;
                    }
        }
        __syncthreads();
    }

    // ======== Stage 2: D = QR @ S_pref (warp tile 32x64) =======================
    float acc[2][8][4];
#pragma unroll
    for (int a = 0; a < 2; a++)
#pragma unroll
        for (int b = 0; b < 8; b++)
#pragma unroll
            for (int c = 0; c < 4; c++) acc[a][b][c] = 0.f;

    if (ch > 0) {
        for (int sl = 0; sl < 8; sl++) {
            if (sl < 7) { stageQ((sl+1)&1, sl+1); stageRS((sl+1)&1, sl+1, Sh, Sl); }
            else        { stageRS(0, 0, Vh, Vl); }
            CP_COMMIT(); CP_WAIT1();
            __syncthreads();
            uint32_t ab = sb + (sl & 1) * AT_BUF_A;
            uint32_t bb = sb + AT_B0 + (sl & 1) * AT_BUF_B;
#pragma unroll
            for (int k0 = 0; k0 < 32; k0 += 16) {
                uint32_t ah[2][4], al[2][4];
#pragma unroll
                for (int mt = 0; mt < 2; mt++) {
                    uint32_t off = (uint32_t)(((wm * 32 + mt * 16 + lm16) * 40 +
                                               k0 + 8 * l16) * 2);
                    ldsm4(ah[mt], ab + off);
                    ldsm4(al[mt], ab + 10240 + off);
                }
#pragma unroll
                for (int np = 0; np < 4; np++) {
                    uint32_t bh2[4], bl2[4];
                    uint32_t off = (uint32_t)(((k0 + lmod8 + 8 * l8) * 264 +
                                               wn * 64 + np * 16 + 8 * l16) * 2);
                    ldsm4t(bh2, bb + off);
                    ldsm4t(bl2, bb + 16896 + off);
#pragma unroll
                    for (int mt = 0; mt < 2; mt++) {
                        mma_bf16(acc[mt][2*np],   ah[mt], bh2);
                        mma_bf16(acc[mt][2*np],   ah[mt], bl2);
                        mma_bf16(acc[mt][2*np],   al[mt], bh2);
                        mma_bf16(acc[mt][2*np+1], ah[mt], bh2 + 2);
                        mma_bf16(acc[mt][2*np+1], ah[mt], bl2 + 2);
                        mma_bf16(acc[mt][2*np+1], al[mt], bh2 + 2);
                    }
                }
            }
            __syncthreads();
        }
    }

    // ======== Stage 3: D += P @ V — skip slabs above warp's diagonal ===========
    for (int sl = 0; sl < 4; sl++) {
        if (sl < 3) { stageRS((sl+1)&1, sl+1, Vh, Vl); CP_COMMIT(); CP_WAIT1(); }
        else        { CP_WAIT0(); }
        __syncthreads();
        if (sl <= wm) {                        // P[r][s]=0 for s >= r
            int s0 = sl * 32;
            uint32_t bb = sb + AT_B0 + (sl & 1) * AT_BUF_B;
#pragma unroll
            for (int k0 = 0; k0 < 32; k0 += 16) {
                uint32_t ah[2][4], al[2][4];
#pragma unroll
                for (int mt = 0; mt < 2; mt++) {
                    uint32_t off = (uint32_t)(((wm * 32 + mt * 16 + lm16) * 136 +
                                               s0 + k0 + 8 * l16) * 2);
                    ldsm4(ah[mt], sb + AT_PH + off);
                    ldsm4(al[mt], sb + AT_PL + off);
                }
#pragma unroll
                for (int np = 0; np < 4; np++) {
                    uint32_t bh2[4], bl2[4];
                    uint32_t off = (uint32_t)(((k0 + lmod8 + 8 * l8) * 264 +
                                               wn * 64 + np * 16 + 8 * l16) * 2);
                    ldsm4t(bh2, bb + off);
                    ldsm4t(bl2, bb + 16896 + off);
#pragma unroll
                    for (int mt = 0; mt < 2; mt++) {
                        mma_bf16(acc[mt][2*np],   ah[mt], bh2);
                        mma_bf16(acc[mt][2*np],   ah[mt], bl2);
                        mma_bf16(acc[mt][2*np],   al[mt], bh2);
                        mma_bf16(acc[mt][2*np+1], ah[mt], bh2 + 2);
                        mma_bf16(acc[mt][2*np+1], ah[mt], bl2 + 2);
                        mma_bf16(acc[mt][2*np+1], al[mt], bh2 + 2);
                    }
                }
            }
        }
        __syncthreads();
    }

    // epilogue
#pragma unroll
    for (int mt = 0; mt < 2; mt++)
#pragma unroll
        for (int nt = 0; nt < 8; nt++)
#pragma unroll
            for (int h = 0; h < 2; h++) {
                int rr = wm * 32 + mt * 16 + lq + 8 * h;
                int cc = wn * 64 + nt * 8 + lr2;
                float2 o; o.x = acc[mt][nt][2*h]; o.y = acc[mt][nt][2*h+1];
                *(float2*)(out + (size_t)(bh * TT + t0 + rr) * NN + cc) = o;
            }
}

// ---------------- launcher -------------------------------------------------------
extern "C" void kernel_launch(void* const* d_in, const int* in_sizes, int n_in,
                              void* d_out, int out_size) {
    const float* Q = (const float*)d_in[0];
    const float* K = (const float*)d_in[1];
    const float* V = (const float*)d_in[2];
    float* out = (float*)d_out;

    static bool attr_set = false;
    if (!attr_set) {
        cudaFuncSetAttribute(k_kv,   cudaFuncAttributeMaxDynamicSharedMemorySize, SMEM_KV);
        cudaFuncSetAttribute(k_attn, cudaFuncAttributeMaxDynamicSharedMemorySize, SMEM_ATTN);
        attr_set = true;
    }

    k_tables<<<512, 512>>>();
    int prep_total = 3 * BH * TT * (NN / 4);
    k_prep<<<(prep_total + 255) / 256, 256>>>(Q, K, V);
    k_kv<<<dim3(BH * (NCH - 1), 2), 512, SMEM_KV>>>();
    k_scan<<<(BH * NN * NN / 4 + 255) / 256, 256>>>();
    k_attn<<<BH * NCH, 512, SMEM_ATTN>>>(out);
}

// round 9
// speedup vs baseline: 2.2768x; 1.0171x over previous
#include <cuda_runtime.h>
#include <cuda_bf16.h>
#include <math.h>
#include <stdint.h>

#define BH   24
#define TT   2048
#define NN   256
#define CC   128
#define NCH  16

// ---------------- device scratch ----------------------------------------------
__device__ float g_tabc[TT * (NN/2)];
__device__ float g_tabs[TT * (NN/2)];
__device__ float g_S[BH*NCH*NN*NN];
__device__ __nv_bfloat16 g_Sh[BH*NCH*NN*NN], g_Sl[BH*NCH*NN*NN];

// ---------------- PTX helpers ---------------------------------------------------
__device__ __forceinline__ uint32_t smem_u32(const void* p) {
    uint32_t a;
    asm("{ .reg .u64 t; cvta.to.shared.u64 t, %1; cvt.u32.u64 %0, t; }" : "=r"(a) : "l"(p));
    return a;
}
__device__ __forceinline__ void cpa16(uint32_t s, const void* g) {
    asm volatile("cp.async.cg.shared.global [%0], [%1], 16;" :: "r"(s), "l"(g));
}
#define CP_COMMIT() asm volatile("cp.async.commit_group;" ::: "memory")
#define CP_WAIT0()  asm volatile("cp.async.wait_group 0;" ::: "memory")

__device__ __forceinline__ void ldsm4(uint32_t* r, uint32_t a) {
    asm volatile("ldmatrix.sync.aligned.m8n8.x4.shared.b16 {%0,%1,%2,%3}, [%4];"
        : "=r"(r[0]), "=r"(r[1]), "=r"(r[2]), "=r"(r[3]) : "r"(a));
}
__device__ __forceinline__ void ldsm4t(uint32_t* r, uint32_t a) {
    asm volatile("ldmatrix.sync.aligned.m8n8.x4.trans.shared.b16 {%0,%1,%2,%3}, [%4];"
        : "=r"(r[0]), "=r"(r[1]), "=r"(r[2]), "=r"(r[3]) : "r"(a));
}
__device__ __forceinline__ void mma_bf16(float* d, const uint32_t* a, const uint32_t* b) {
    asm volatile("mma.sync.aligned.m16n8k16.row.col.f32.bf16.bf16.f32 "
        "{%0,%1,%2,%3}, {%4,%5,%6,%7}, {%8,%9}, {%0,%1,%2,%3};"
        : "+f"(d[0]), "+f"(d[1]), "+f"(d[2]), "+f"(d[3])
        : "r"(a[0]), "r"(a[1]), "r"(a[2]), "r"(a[3]), "r"(b[0]), "r"(b[1]));
}

// ---------------- split / rope helpers ------------------------------------------
__device__ __forceinline__ void split2(float x, float y, uint32_t& h, uint32_t& l) {
    __nv_bfloat16 hx = __float2bfloat16(x), hy = __float2bfloat16(y);
    __nv_bfloat162 H; H.x = hx; H.y = hy;
    __nv_bfloat162 L;
    L.x = __float2bfloat16(x - __bfloat162float(hx));
    L.y = __float2bfloat16(y - __bfloat162float(hy));
    h = *(uint32_t*)&H; l = *(uint32_t*)&L;
}
// rope+split 8 consecutive features at (token t, feature f, f%8==0), preloaded c/s
__device__ __forceinline__ void rope_split8_cs(const float* __restrict__ src,
                                               float4 c, float4 s,
                                               uint4& hi, uint4& lo) {
    float4 a = *(const float4*)(src);
    float4 b = *(const float4*)(src + 4);
    float r0 = a.x*c.x - a.y*s.x, r1 = a.y*c.x + a.x*s.x;
    float r2 = a.z*c.y - a.w*s.y, r3 = a.w*c.y + a.z*s.y;
    float r4 = b.x*c.z - b.y*s.z, r5 = b.y*c.z + b.x*s.z;
    float r6 = b.z*c.w - b.w*s.w, r7 = b.w*c.w + b.z*s.w;
    split2(r0, r1, hi.x, lo.x); split2(r2, r3, hi.y, lo.y);
    split2(r4, r5, hi.z, lo.z); split2(r6, r7, hi.w, lo.w);
}
__device__ __forceinline__ void rope_split8(const float* __restrict__ src, int t, int f,
                                            uint4& hi, uint4& lo) {
    float4 c = *(const float4*)(g_tabc + t * 128 + (f >> 1));
    float4 s = *(const float4*)(g_tabs + t * 128 + (f >> 1));
    rope_split8_cs(src, c, s, hi, lo);
}
__device__ __forceinline__ void split8(const float* __restrict__ src, uint4& hi, uint4& lo) {
    float4 a = *(const float4*)(src);
    float4 b = *(const float4*)(src + 4);
    split2(a.x, a.y, hi.x, lo.x); split2(a.z, a.w, hi.y, lo.y);
    split2(b.x, b.y, hi.z, lo.z); split2(b.z, b.w, hi.w, lo.w);
}

// ---------------- kernel 1: RoPE phase tables -----------------------------------
__global__ void k_tables() {
    int id = blockIdx.x * blockDim.x + threadIdx.x;
    if (id >= TT * (NN/2)) return;
    int t = id >> 7;
    int j = id & 127;
    double fr_d = exp2(-(double)j / 8.0) / (2.0 * 3.14159265358979323846);
    float f32 = (float)fr_d;
    float ph  = (float)t * f32;
    ph = ph - floorf(ph);
    float ang = ph * 6.28318530717958647692f;
    double angd = (double)ang;
    g_tabc[id] = (float)cos(angd);
    g_tabs[id] = (float)sin(angd);
}

// ---------------- kernel 2: chunk KV state S_ch = KR^T @ V (fused rope) ---------
#define KV_BUF_A 17408
#define KV_BUF_B 33792
#define KV_B0    34816
#define SMEM_KV  102400

__global__ void __launch_bounds__(512, 1) k_kv(const float* __restrict__ K,
                                               const float* __restrict__ V) {
    extern __shared__ char sm[];
    uint32_t sb = smem_u32(sm);
    int tid = threadIdx.x, lane = tid & 31, wid = tid >> 5;
    int wm = wid >> 2, wn = wid & 3;
    int bx = blockIdx.x;
    int bh = bx / 15, ch = bx % 15;
    int m0g = blockIdx.y * 128;
    int t0 = ch * CC;
    int l16 = lane >> 4, lmod8 = lane & 7, l8 = (lane >> 3) & 1;
    int lq = lane >> 2, lr2 = (lane & 3) * 2;

    const float* Kp = K + (size_t)(bh * TT + t0) * NN;
    const float* Vp = V + (size_t)(bh * TT + t0) * NN;

    // staging coords
    int ar = tid >> 4, ac8 = tid & 15;              // A (K^T): 32 rows x 128 feats
    uint32_t a_so = (uint32_t)(ar * 272 + ac8 * 16);
    int vr = tid >> 5, vc8 = tid & 31;              // B (V): 32 rows x 256 feats, 2 iters
    uint32_t v_so = (uint32_t)(vr * 528 + vc8 * 16);

    uint4 ahi, alo, vhi0, vlo0, vhi1, vlo1;
    auto loadSlab = [&](int sl) {
        int tk = t0 + sl * 32 + ar;
        rope_split8(Kp + (size_t)(sl * 32 + ar) * NN + m0g + ac8 * 8,
                    tk, m0g + ac8 * 8, ahi, alo);
        split8(Vp + (size_t)(sl * 32 + vr) * NN + vc8 * 8, vhi0, vlo0);
        split8(Vp + (size_t)(sl * 32 + vr + 16) * NN + vc8 * 8, vhi1, vlo1);
    };
    auto storeSlab = [&](int buf) {
        char* ab = sm + buf * KV_BUF_A;
        *(uint4*)(ab + a_so) = ahi;
        *(uint4*)(ab + 8704 + a_so) = alo;
        char* bb = sm + KV_B0 + buf * KV_BUF_B;
        *(uint4*)(bb + v_so) = vhi0;
        *(uint4*)(bb + 16896 + v_so) = vlo0;
        *(uint4*)(bb + 8448 + v_so) = vhi1;
        *(uint4*)(bb + 16896 + 8448 + v_so) = vlo1;
    };

    float acc[2][8][4];
#pragma unroll
    for (int a = 0; a < 2; a++)
#pragma unroll
        for (int b = 0; b < 8; b++)
#pragma unroll
            for (int c = 0; c < 4; c++) acc[a][b][c] = 0.f;

    loadSlab(0);
    storeSlab(0);
    __syncthreads();
    for (int sl = 0; sl < 4; sl++) {
        if (sl < 3) loadSlab(sl + 1);
        uint32_t ab = sb + (sl & 1) * KV_BUF_A;
        uint32_t bb = sb + KV_B0 + (sl & 1) * KV_BUF_B;
#pragma unroll
        for (int k0 = 0; k0 < 32; k0 += 16) {
            uint32_t ah[2][4], al[2][4];
#pragma unroll
            for (int mt = 0; mt < 2; mt++) {
                uint32_t off = (uint32_t)(((k0 + lmod8 + 8 * l16) * 136 +
                                           wm * 32 + mt * 16 + 8 * l8) * 2);
                ldsm4t(ah[mt], ab + off);
                ldsm4t(al[mt], ab + 8704 + off);
            }
#pragma unroll
            for (int np = 0; np < 4; np++) {
                uint32_t bh2[4], bl2[4];
                uint32_t off = (uint32_t)(((k0 + lmod8 + 8 * l8) * 264 +
                                           wn * 64 + np * 16 + 8 * l16) * 2);
                ldsm4t(bh2, bb + off);
                ldsm4t(bl2, bb + 16896 + off);
#pragma unroll
                for (int mt = 0; mt < 2; mt++) {
                    mma_bf16(acc[mt][2*np],   ah[mt], bh2);
                    mma_bf16(acc[mt][2*np],   ah[mt], bl2);
                    mma_bf16(acc[mt][2*np],   al[mt], bh2);
                    mma_bf16(acc[mt][2*np+1], ah[mt], bh2 + 2);
                    mma_bf16(acc[mt][2*np+1], ah[mt], bl2 + 2);
                    mma_bf16(acc[mt][2*np+1], al[mt], bh2 + 2);
                }
            }
        }
        if (sl < 3) { storeSlab((sl + 1) & 1); __syncthreads(); }
    }
    float* Sp = g_S + (size_t)(bh * NCH + ch) * (NN * NN);
#pragma unroll
    for (int mt = 0; mt < 2; mt++)
#pragma unroll
        for (int nt = 0; nt < 8; nt++)
#pragma unroll
            for (int h = 0; h < 2; h++) {
                int rr = m0g + wm * 32 + mt * 16 + lq + 8 * h;
                int cc = wn * 64 + nt * 8 + lr2;
                float2 o; o.x = acc[mt][nt][2*h]; o.y = acc[mt][nt][2*h+1];
                *(float2*)(Sp + (size_t)rr * NN + cc) = o;
            }
}

// ---------------- kernel 3: exclusive prefix scan + bf16 split (MLP) ------------
__global__ void k_scan() {
    int g = blockIdx.x * blockDim.x + threadIdx.x;
    if (g >= BH * NN * NN / 4) return;
    int bh = g >> 14;
    int e4 = (g & 16383) << 2;
    size_t base = (size_t)bh * NCH * (NN * NN) + e4;
    float4 vals[NCH - 1];
#pragma unroll
    for (int i = 0; i < NCH - 1; i++)
        vals[i] = *(const float4*)(g_S + base + (size_t)i * (NN * NN));
    float r0 = 0.f, r1 = 0.f, r2 = 0.f, r3 = 0.f;
#pragma unroll
    for (int i = 0; i < NCH; i++) {
        size_t p = base + (size_t)i * (NN * NN);
        __nv_bfloat16 h0 = __float2bfloat16(r0), h1 = __float2bfloat16(r1);
        __nv_bfloat16 h2 = __float2bfloat16(r2), h3 = __float2bfloat16(r3);
        __nv_bfloat162 H[2], L[2];
        H[0].x = h0; H[0].y = h1; H[1].x = h2; H[1].y = h3;
        L[0].x = __float2bfloat16(r0 - __bfloat162float(h0));
        L[0].y = __float2bfloat16(r1 - __bfloat162float(h1));
        L[1].x = __float2bfloat16(r2 - __bfloat162float(h2));
        L[1].y = __float2bfloat16(r3 - __bfloat162float(h3));
        *(uint2*)(g_Sh + p) = *(uint2*)H;
        *(uint2*)(g_Sl + p) = *(uint2*)L;
        if (i < NCH - 1) { r0 += vals[i].x; r1 += vals[i].y; r2 += vals[i].z; r3 += vals[i].w; }
    }
}

// ---------------- kernel 4: Out = QR@S_pref + strict_tril(QR@KR^T)@V ------------
#define AT_BUF_A 20480
#define AT_B0    40960
#define AT_BUF_B 33792
#define AT_PH    108544
#define AT_PL    143360
#define SMEM_ATTN 178176

// stage-1 warp->tile LUT (10 live lower-triangle tiles, 3/3/2/2 per SMSP)
#define S1_R_PACK 981476u
#define S1_C_PACK 54436u

__global__ void __launch_bounds__(512, 1) k_attn(const float* __restrict__ Q,
                                                 const float* __restrict__ K,
                                                 const float* __restrict__ V,
                                                 float* __restrict__ out) {
    extern __shared__ char sm[];
    uint32_t sb = smem_u32(sm);
    int tid = threadIdx.x, lane = tid & 31, wid = tid >> 5;
    int wm = wid >> 2, wn = wid & 3;
    int bh = blockIdx.x >> 4, ch = 15 - (blockIdx.x & 15);
    int t0 = ch * CC;
    int lm16 = lane & 15, l16 = lane >> 4, lmod8 = lane & 7, l8 = (lane >> 3) & 1;
    int lq = lane >> 2, lr2 = (lane & 3) * 2;

    const float* Qp = Q + (size_t)(bh * TT + t0) * NN;
    const float* Kp = K + (size_t)(bh * TT + t0) * NN;
    const float* Vp = V + (size_t)(bh * TT + t0) * NN;
    const __nv_bfloat16* Sh = g_Sh + (size_t)(bh * NCH + ch) * (NN * NN);
    const __nv_bfloat16* Sl = g_Sl + (size_t)(bh * NCH + ch) * (NN * NN);

    // staging coords: Q/K slabs [128 rows][40], one 8-feature group per thread
    int sr = tid >> 2, sc8 = tid & 3;
    uint32_t s_so = (uint32_t)(sr * 80 + sc8 * 16);
    // V slabs [32 rows][264], 2 iters
    int vr = tid >> 5, vc8 = tid & 31;
    uint32_t v_so = (uint32_t)(vr * 528 + vc8 * 16);

    // ======== Stage 1: P = QR @ KR^T, lower-triangle tiles only ================
    {
        int pr = (S1_R_PACK >> (wid * 2)) & 3;
        int pc = (S1_C_PACK >> (wid * 2)) & 3;
        bool act1 = (wid < 10);

        uint4 qhi, qlo, khi, klo;
        auto loadQK = [&](int sl) {
            int f = sl * 32 + sc8 * 8;
            float4 c = *(const float4*)(g_tabc + (t0 + sr) * 128 + (f >> 1));
            float4 s = *(const float4*)(g_tabs + (t0 + sr) * 128 + (f >> 1));
            rope_split8_cs(Qp + (size_t)sr * NN + f, c, s, qhi, qlo);
            rope_split8_cs(Kp + (size_t)sr * NN + f, c, s, khi, klo);
        };
        auto storeQK = [&](int buf) {
            char* ab = sm + buf * AT_BUF_A;
            *(uint4*)(ab + s_so) = qhi;
            *(uint4*)(ab + 10240 + s_so) = qlo;
            char* bb = sm + AT_B0 + buf * AT_BUF_B;
            *(uint4*)(bb + s_so) = khi;
            *(uint4*)(bb + 16896 + s_so) = klo;
        };

        float acc1[2][4][4];
#pragma unroll
        for (int a = 0; a < 2; a++)
#pragma unroll
            for (int b = 0; b < 4; b++)
#pragma unroll
                for (int c = 0; c < 4; c++) acc1[a][b][c] = 0.f;

        loadQK(0);
        storeQK(0);
        __syncthreads();
        for (int sl = 0; sl < 8; sl++) {
            if (sl < 7) loadQK(sl + 1);
            if (act1) {
                uint32_t ab = sb + (sl & 1) * AT_BUF_A;
                uint32_t bb = sb + AT_B0 + (sl & 1) * AT_BUF_B;
#pragma unroll
                for (int k0 = 0; k0 < 32; k0 += 16) {
                    uint32_t ah[2][4], al[2][4];
#pragma unroll
                    for (int mt = 0; mt < 2; mt++) {
                        uint32_t off = (uint32_t)(((pr * 32 + mt * 16 + lm16) * 40 +
                                                   k0 + 8 * l16) * 2);
                        ldsm4(ah[mt], ab + off);
                        ldsm4(al[mt], ab + 10240 + off);
                    }
#pragma unroll
                    for (int np = 0; np < 2; np++) {
                        uint32_t bh2[4], bl2[4];
                        uint32_t off = (uint32_t)(((pc * 32 + np * 16 + lmod8 + 8 * l16) * 40 +
                                                   k0 + 8 * l8) * 2);
                        ldsm4(bh2, bb + off);
                        ldsm4(bl2, bb + 16896 + off);
#pragma unroll
                        for (int mt = 0; mt < 2; mt++) {
                            mma_bf16(acc1[mt][2*np],   ah[mt], bh2);
                            mma_bf16(acc1[mt][2*np],   ah[mt], bl2);
                            mma_bf16(acc1[mt][2*np],   al[mt], bh2);
                            mma_bf16(acc1[mt][2*np+1], ah[mt], bh2 + 2);
                            mma_bf16(acc1[mt][2*np+1], ah[mt], bl2 + 2);
                            mma_bf16(acc1[mt][2*np+1], al[mt], bh2 + 2);
                        }
                    }
                }
            }
            if (sl < 7) { storeQK((sl + 1) & 1); __syncthreads(); }
        }
        __syncthreads();
        // mask (strict lower triangle) + bf16 split into smem P (live tiles only)
        if (act1) {
#pragma unroll
            for (int mt = 0; mt < 2; mt++)
#pragma unroll
                for (int nt = 0; nt < 4; nt++)
#pragma unroll
                    for (int h = 0; h < 2; h++) {
                        int rr = pr * 32 + mt * 16 + lq + 8 * h;
                        int cn = pc * 32 + nt * 8 + lr2;
                        float v0 = (cn     < rr) ? acc1[mt][nt][2*h]   : 0.f;
                        float v1 = (cn + 1 < rr) ? acc1[mt][nt][2*h+1] : 0.f;
                        uint32_t hbits, lbits;
                        split2(v0, v1, hbits, lbits);
                        uint32_t bo = (uint32_t)((rr * 136 + cn) * 2);
                        *(uint32_t*)(sm + AT_PH + bo) = hbits;
                        *(uint32_t*)(sm + AT_PL + bo) = lbits;
                    }
        }
        __syncthreads();
    }

    // ======== Stage 2: D = QR @ S_pref (warp tile 32x64) =======================
    float acc[2][8][4];
#pragma unroll
    for (int a = 0; a < 2; a++)
#pragma unroll
        for (int b = 0; b < 8; b++)
#pragma unroll
            for (int c = 0; c < 4; c++) acc[a][b][c] = 0.f;

    if (ch > 0) {
        uint4 qhi, qlo;
        auto loadQ2 = [&](int sl) {
            int f = sl * 32 + sc8 * 8;
            float4 c = *(const float4*)(g_tabc + (t0 + sr) * 128 + (f >> 1));
            float4 s = *(const float4*)(g_tabs + (t0 + sr) * 128 + (f >> 1));
            rope_split8_cs(Qp + (size_t)sr * NN + f, c, s, qhi, qlo);
        };
        auto storeQ2 = [&](int buf) {
            char* ab = sm + buf * AT_BUF_A;
            *(uint4*)(ab + s_so) = qhi;
            *(uint4*)(ab + 10240 + s_so) = qlo;
        };
        auto cpS = [&](int buf, int sl) {
            uint32_t bb = sb + AT_B0 + buf * AT_BUF_B;
            int f0 = sl * 32;
#pragma unroll
            for (int v = tid; v < 1024; v += 512) {
                int r = v >> 5, c8 = v & 31;
                uint32_t so = (uint32_t)(r * 528 + c8 * 16);
                cpa16(bb + so,         Sh + (size_t)(f0 + r) * NN + c8 * 8);
                cpa16(bb + 16896 + so, Sl + (size_t)(f0 + r) * NN + c8 * 8);
            }
        };

        loadQ2(0); cpS(0, 0); CP_COMMIT();
        storeQ2(0); CP_WAIT0();
        __syncthreads();
        for (int sl = 0; sl < 8; sl++) {
            if (sl < 7) { loadQ2(sl + 1); cpS((sl + 1) & 1, sl + 1); CP_COMMIT(); }
            uint32_t ab = sb + (sl & 1) * AT_BUF_A;
            uint32_t bb = sb + AT_B0 + (sl & 1) * AT_BUF_B;
#pragma unroll
            for (int k0 = 0; k0 < 32; k0 += 16) {
                uint32_t ah[2][4], al[2][4];
#pragma unroll
                for (int mt = 0; mt < 2; mt++) {
                    uint32_t off = (uint32_t)(((wm * 32 + mt * 16 + lm16) * 40 +
                                               k0 + 8 * l16) * 2);
                    ldsm4(ah[mt], ab + off);
                    ldsm4(al[mt], ab + 10240 + off);
                }
#pragma unroll
                for (int np = 0; np < 4; np++) {
                    uint32_t bh2[4], bl2[4];
                    uint32_t off = (uint32_t)(((k0 + lmod8 + 8 * l8) * 264 +
                                               wn * 64 + np * 16 + 8 * l16) * 2);
                    ldsm4t(bh2, bb + off);
                    ldsm4t(bl2, bb + 16896 + off);
#pragma unroll
                    for (int mt = 0; mt < 2; mt++) {
                        mma_bf16(acc[mt][2*np],   ah[mt], bh2);
                        mma_bf16(acc[mt][2*np],   ah[mt], bl2);
                        mma_bf16(acc[mt][2*np],   al[mt], bh2);
                        mma_bf16(acc[mt][2*np+1], ah[mt], bh2 + 2);
                        mma_bf16(acc[mt][2*np+1], ah[mt], bl2 + 2);
                        mma_bf16(acc[mt][2*np+1], al[mt], bh2 + 2);
                    }
                }
            }
            if (sl < 7) { storeQ2((sl + 1) & 1); CP_WAIT0(); __syncthreads(); }
        }
    }

    // ======== Stage 3: D += P @ V — skip slabs above warp's diagonal ===========
    {
        uint4 vhi0, vlo0, vhi1, vlo1;
        auto loadV3 = [&](int sl) {
            split8(Vp + (size_t)(sl * 32 + vr) * NN + vc8 * 8, vhi0, vlo0);
            split8(Vp + (size_t)(sl * 32 + vr + 16) * NN + vc8 * 8, vhi1, vlo1);
        };
        auto storeV3 = [&](int buf) {
            char* bb = sm + AT_B0 + buf * AT_BUF_B;
            *(uint4*)(bb + v_so) = vhi0;
            *(uint4*)(bb + 16896 + v_so) = vlo0;
            *(uint4*)(bb + 8448 + v_so) = vhi1;
            *(uint4*)(bb + 16896 + 8448 + v_so) = vlo1;
        };

        loadV3(0);
        storeV3(0);
        __syncthreads();
        for (int sl = 0; sl < 4; sl++) {
            if (sl < 3) loadV3(sl + 1);
            if (sl <= wm) {
                int s0 = sl * 32;
                uint32_t bb = sb + AT_B0 + (sl & 1) * AT_BUF_B;
#pragma unroll
                for (int k0 = 0; k0 < 32; k0 += 16) {
                    uint32_t ah[2][4], al[2][4];
#pragma unroll
                    for (int mt = 0; mt < 2; mt++) {
                        uint32_t off = (uint32_t)(((wm * 32 + mt * 16 + lm16) * 136 +
                                                   s0 + k0 + 8 * l16) * 2);
                        ldsm4(ah[mt], sb + AT_PH + off);
                        ldsm4(al[mt], sb + AT_PL + off);
                    }
#pragma unroll
                    for (int np = 0; np < 4; np++) {
                        uint32_t bh2[4], bl2[4];
                        uint32_t off = (uint32_t)(((k0 + lmod8 + 8 * l8) * 264 +
                                                   wn * 64 + np * 16 + 8 * l16) * 2);
                        ldsm4t(bh2, bb + off);
                        ldsm4t(bl2, bb + 16896 + off);
#pragma unroll
                        for (int mt = 0; mt < 2; mt++) {
                            mma_bf16(acc[mt][2*np],   ah[mt], bh2);
                            mma_bf16(acc[mt][2*np],   ah[mt], bl2);
                            mma_bf16(acc[mt][2*np],   al[mt], bh2);
                            mma_bf16(acc[mt][2*np+1], ah[mt], bh2 + 2);
                            mma_bf16(acc[mt][2*np+1], ah[mt], bl2 + 2);
                            mma_bf16(acc[mt][2*np+1], al[mt], bh2 + 2);
                        }
                    }
                }
            }
            if (sl < 3) { storeV3((sl + 1) & 1); __syncthreads(); }
        }
    }

    // epilogue
#pragma unroll
    for (int mt = 0; mt < 2; mt++)
#pragma unroll
        for (int nt = 0; nt < 8; nt++)
#pragma unroll
            for (int h = 0; h < 2; h++) {
                int rr = wm * 32 + mt * 16 + lq + 8 * h;
                int cc = wn * 64 + nt * 8 + lr2;
                float2 o; o.x = acc[mt][nt][2*h]; o.y = acc[mt][nt][2*h+1];
                *(float2*)(out + (size_t)(bh * TT + t0 + rr) * NN + cc) = o;
            }
}

// ---------------- launcher (single stream, no prep kernel) -----------------------
extern "C" void kernel_launch(void* const* d_in, const int* in_sizes, int n_in,
                              void* d_out, int out_size) {
    const float* Q = (const float*)d_in[0];
    const float* K = (const float*)d_in[1];
    const float* V = (const float*)d_in[2];
    float* out = (float*)d_out;

    static bool attr_set = false;
    if (!attr_set) {
        cudaFuncSetAttribute(k_kv,   cudaFuncAttributeMaxDynamicSharedMemorySize, SMEM_KV);
        cudaFuncSetAttribute(k_attn, cudaFuncAttributeMaxDynamicSharedMemorySize, SMEM_ATTN);
        attr_set = true;
    }

    k_tables<<<512, 512>>>();
    k_kv<<<dim3(BH * (NCH - 1), 2), 512, SMEM_KV>>>(K, V);
    k_scan<<<(BH * NN * NN / 4 + 255) / 256, 256>>>();
    k_attn<<<BH * NCH, 512, SMEM_ATTN>>>(Q, K, V, out);
}

// round 10
// speedup vs baseline: 2.3067x; 1.0131x over previous
#include <cuda_runtime.h>
#include <cuda_bf16.h>
#include <math.h>
#include <stdint.h>

#define BH   24
#define TT   2048
#define NN   256
#define CC   128
#define NCH  16

// ---------------- device scratch ----------------------------------------------
__device__ float g_tabc[TT * (NN/2)];
__device__ float g_tabs[TT * (NN/2)];
__device__ float g_S[BH*NCH*NN*NN];
__device__ __nv_bfloat16 g_Sh[BH*NCH*NN*NN], g_Sl[BH*NCH*NN*NN];

// ---------------- PTX helpers ---------------------------------------------------
__device__ __forceinline__ uint32_t smem_u32(const void* p) {
    uint32_t a;
    asm("{ .reg .u64 t; cvta.to.shared.u64 t, %1; cvt.u32.u64 %0, t; }" : "=r"(a) : "l"(p));
    return a;
}
__device__ __forceinline__ void cpa16(uint32_t s, const void* g) {
    asm volatile("cp.async.cg.shared.global [%0], [%1], 16;" :: "r"(s), "l"(g));
}
#define CP_COMMIT() asm volatile("cp.async.commit_group;" ::: "memory")
#define CP_WAIT0()  asm volatile("cp.async.wait_group 0;" ::: "memory")

__device__ __forceinline__ void ldsm4(uint32_t* r, uint32_t a) {
    asm volatile("ldmatrix.sync.aligned.m8n8.x4.shared.b16 {%0,%1,%2,%3}, [%4];"
        : "=r"(r[0]), "=r"(r[1]), "=r"(r[2]), "=r"(r[3]) : "r"(a));
}
__device__ __forceinline__ void ldsm4t(uint32_t* r, uint32_t a) {
    asm volatile("ldmatrix.sync.aligned.m8n8.x4.trans.shared.b16 {%0,%1,%2,%3}, [%4];"
        : "=r"(r[0]), "=r"(r[1]), "=r"(r[2]), "=r"(r[3]) : "r"(a));
}
__device__ __forceinline__ void mma_bf16(float* d, const uint32_t* a, const uint32_t* b) {
    asm volatile("mma.sync.aligned.m16n8k16.row.col.f32.bf16.bf16.f32 "
        "{%0,%1,%2,%3}, {%4,%5,%6,%7}, {%8,%9}, {%0,%1,%2,%3};"
        : "+f"(d[0]), "+f"(d[1]), "+f"(d[2]), "+f"(d[3])
        : "r"(a[0]), "r"(a[1]), "r"(a[2]), "r"(a[3]), "r"(b[0]), "r"(b[1]));
}

// ---------------- split / rope helpers (packed cvt path) ------------------------
// h = {lo16=bf16(x), hi16=bf16(y)}; l = residual pair. Bit-identical to the
// scalar __float2bfloat16 path (same .rn rounding), ~40% fewer instructions.
__device__ __forceinline__ void split2(float x, float y, uint32_t& h, uint32_t& l) {
    uint32_t hb;
    asm("cvt.rn.bf16x2.f32 %0, %1, %2;" : "=r"(hb) : "f"(y), "f"(x));
    float hx = __uint_as_float(hb << 16);
    float hy = __uint_as_float(hb & 0xFFFF0000u);
    float lx = x - hx, ly = y - hy;
    asm("cvt.rn.bf16x2.f32 %0, %1, %2;" : "=r"(l) : "f"(ly), "f"(lx));
    h = hb;
}
__device__ __forceinline__ void rope_split8_cs(const float* __restrict__ src,
                                               float4 c, float4 s,
                                               uint4& hi, uint4& lo) {
    float4 a = *(const float4*)(src);
    float4 b = *(const float4*)(src + 4);
    float r0 = a.x*c.x - a.y*s.x, r1 = a.y*c.x + a.x*s.x;
    float r2 = a.z*c.y - a.w*s.y, r3 = a.w*c.y + a.z*s.y;
    float r4 = b.x*c.z - b.y*s.z, r5 = b.y*c.z + b.x*s.z;
    float r6 = b.z*c.w - b.w*s.w, r7 = b.w*c.w + b.z*s.w;
    split2(r0, r1, hi.x, lo.x); split2(r2, r3, hi.y, lo.y);
    split2(r4, r5, hi.z, lo.z); split2(r6, r7, hi.w, lo.w);
}
__device__ __forceinline__ void rope_split8(const float* __restrict__ src, int t, int f,
                                            uint4& hi, uint4& lo) {
    float4 c = *(const float4*)(g_tabc + t * 128 + (f >> 1));
    float4 s = *(const float4*)(g_tabs + t * 128 + (f >> 1));
    rope_split8_cs(src, c, s, hi, lo);
}
__device__ __forceinline__ void split8(const float* __restrict__ src, uint4& hi, uint4& lo) {
    float4 a = *(const float4*)(src);
    float4 b = *(const float4*)(src + 4);
    split2(a.x, a.y, hi.x, lo.x); split2(a.z, a.w, hi.y, lo.y);
    split2(b.x, b.y, hi.z, lo.z); split2(b.z, b.w, hi.w, lo.w);
}

// ---------------- kernel 1: RoPE phase tables -----------------------------------
__global__ void k_tables() {
    int id = blockIdx.x * blockDim.x + threadIdx.x;
    if (id >= TT * (NN/2)) return;
    int t = id >> 7;
    int j = id & 127;
    double fr_d = exp2(-(double)j / 8.0) / (2.0 * 3.14159265358979323846);
    float f32 = (float)fr_d;
    float ph  = (float)t * f32;
    ph = ph - floorf(ph);
    float ang = ph * 6.28318530717958647692f;
    double angd = (double)ang;
    g_tabc[id] = (float)cos(angd);
    g_tabs[id] = (float)sin(angd);
}

// ---------------- kernel 2: chunk KV state S_ch = KR^T @ V (fused rope) ---------
#define KV_BUF_A 17408
#define KV_BUF_B 33792
#define KV_B0    34816
#define SMEM_KV  102400

__global__ void __launch_bounds__(512, 1) k_kv(const float* __restrict__ K,
                                               const float* __restrict__ V) {
    extern __shared__ char sm[];
    uint32_t sb = smem_u32(sm);
    int tid = threadIdx.x, lane = tid & 31, wid = tid >> 5;
    int wm = wid >> 2, wn = wid & 3;
    int bx = blockIdx.x;
    int bh = bx / 15, ch = bx % 15;
    int m0g = blockIdx.y * 128;
    int t0 = ch * CC;
    int l16 = lane >> 4, lmod8 = lane & 7, l8 = (lane >> 3) & 1;
    int lq = lane >> 2, lr2 = (lane & 3) * 2;

    const float* Kp = K + (size_t)(bh * TT + t0) * NN;
    const float* Vp = V + (size_t)(bh * TT + t0) * NN;

    int ar = tid >> 4, ac8 = tid & 15;
    uint32_t a_so = (uint32_t)(ar * 272 + ac8 * 16);
    int vr = tid >> 5, vc8 = tid & 31;
    uint32_t v_so = (uint32_t)(vr * 528 + vc8 * 16);

    uint4 ahi, alo, vhi0, vlo0, vhi1, vlo1;
    auto loadSlab = [&](int sl) {
        int tk = t0 + sl * 32 + ar;
        rope_split8(Kp + (size_t)(sl * 32 + ar) * NN + m0g + ac8 * 8,
                    tk, m0g + ac8 * 8, ahi, alo);
        split8(Vp + (size_t)(sl * 32 + vr) * NN + vc8 * 8, vhi0, vlo0);
        split8(Vp + (size_t)(sl * 32 + vr + 16) * NN + vc8 * 8, vhi1, vlo1);
    };
    auto storeSlab = [&](int buf) {
        char* ab = sm + buf * KV_BUF_A;
        *(uint4*)(ab + a_so) = ahi;
        *(uint4*)(ab + 8704 + a_so) = alo;
        char* bb = sm + KV_B0 + buf * KV_BUF_B;
        *(uint4*)(bb + v_so) = vhi0;
        *(uint4*)(bb + 16896 + v_so) = vlo0;
        *(uint4*)(bb + 8448 + v_so) = vhi1;
        *(uint4*)(bb + 16896 + 8448 + v_so) = vlo1;
    };

    float acc[2][8][4];
#pragma unroll
    for (int a = 0; a < 2; a++)
#pragma unroll
        for (int b = 0; b < 8; b++)
#pragma unroll
            for (int c = 0; c < 4; c++) acc[a][b][c] = 0.f;

    loadSlab(0);
    storeSlab(0);
    __syncthreads();
    for (int sl = 0; sl < 4; sl++) {
        if (sl < 3) loadSlab(sl + 1);
        uint32_t ab = sb + (sl & 1) * KV_BUF_A;
        uint32_t bb = sb + KV_B0 + (sl & 1) * KV_BUF_B;
#pragma unroll
        for (int k0 = 0; k0 < 32; k0 += 16) {
            uint32_t ah[2][4], al[2][4];
#pragma unroll
            for (int mt = 0; mt < 2; mt++) {
                uint32_t off = (uint32_t)(((k0 + lmod8 + 8 * l16) * 136 +
                                           wm * 32 + mt * 16 + 8 * l8) * 2);
                ldsm4t(ah[mt], ab + off);
                ldsm4t(al[mt], ab + 8704 + off);
            }
#pragma unroll
            for (int np = 0; np < 4; np++) {
                uint32_t bh2[4], bl2[4];
                uint32_t off = (uint32_t)(((k0 + lmod8 + 8 * l8) * 264 +
                                           wn * 64 + np * 16 + 8 * l16) * 2);
                ldsm4t(bh2, bb + off);
                ldsm4t(bl2, bb + 16896 + off);
#pragma unroll
                for (int mt = 0; mt < 2; mt++) {
                    mma_bf16(acc[mt][2*np],   ah[mt], bh2);
                    mma_bf16(acc[mt][2*np],   ah[mt], bl2);
                    mma_bf16(acc[mt][2*np],   al[mt], bh2);
                    mma_bf16(acc[mt][2*np+1], ah[mt], bh2 + 2);
                    mma_bf16(acc[mt][2*np+1], ah[mt], bl2 + 2);
                    mma_bf16(acc[mt][2*np+1], al[mt], bh2 + 2);
                }
            }
        }
        if (sl < 3) { storeSlab((sl + 1) & 1); __syncthreads(); }
    }
    float* Sp = g_S + (size_t)(bh * NCH + ch) * (NN * NN);
#pragma unroll
    for (int mt = 0; mt < 2; mt++)
#pragma unroll
        for (int nt = 0; nt < 8; nt++)
#pragma unroll
            for (int h = 0; h < 2; h++) {
                int rr = m0g + wm * 32 + mt * 16 + lq + 8 * h;
                int cc = wn * 64 + nt * 8 + lr2;
                float2 o; o.x = acc[mt][nt][2*h]; o.y = acc[mt][nt][2*h+1];
                *(float2*)(Sp + (size_t)rr * NN + cc) = o;
            }
}

// ---------------- kernel 3: exclusive prefix scan + bf16 split (MLP) ------------
__global__ void k_scan() {
    int g = blockIdx.x * blockDim.x + threadIdx.x;
    if (g >= BH * NN * NN / 4) return;
    int bh = g >> 14;
    int e4 = (g & 16383) << 2;
    size_t base = (size_t)bh * NCH * (NN * NN) + e4;
    float4 vals[NCH - 1];
#pragma unroll
    for (int i = 0; i < NCH - 1; i++)
        vals[i] = *(const float4*)(g_S + base + (size_t)i * (NN * NN));
    float r0 = 0.f, r1 = 0.f, r2 = 0.f, r3 = 0.f;
#pragma unroll
    for (int i = 0; i < NCH; i++) {
        size_t p = base + (size_t)i * (NN * NN);
        uint32_t h01, l01, h23, l23;
        split2(r0, r1, h01, l01);
        split2(r2, r3, h23, l23);
        uint2 H; H.x = h01; H.y = h23;
        uint2 L; L.x = l01; L.y = l23;
        *(uint2*)(g_Sh + p) = H;
        *(uint2*)(g_Sl + p) = L;
        if (i < NCH - 1) { r0 += vals[i].x; r1 += vals[i].y; r2 += vals[i].z; r3 += vals[i].w; }
    }
}

// ---------------- kernel 4: Out = QR@S_pref + strict_tril(QR@KR^T)@V ------------
#define AT_BUF_A 20480
#define AT_B0    40960
#define AT_BUF_B 33792
#define AT_PH    108544
#define AT_PL    143360
#define SMEM_ATTN 178176

// stage-1 warp->tile LUT (10 live lower-triangle tiles, 3/3/2/2 per SMSP)
#define S1_R_PACK 981476u
#define S1_C_PACK 54436u

__global__ void __launch_bounds__(512, 1) k_attn(const float* __restrict__ Q,
                                                 const float* __restrict__ K,
                                                 const float* __restrict__ V,
                                                 float* __restrict__ out) {
    extern __shared__ char sm[];
    uint32_t sb = smem_u32(sm);
    int tid = threadIdx.x, lane = tid & 31, wid = tid >> 5;
    int wm = wid >> 2, wn = wid & 3;
    int bh = blockIdx.x >> 4, ch = 15 - (blockIdx.x & 15);
    int t0 = ch * CC;
    int lm16 = lane & 15, l16 = lane >> 4, lmod8 = lane & 7, l8 = (lane >> 3) & 1;
    int lq = lane >> 2, lr2 = (lane & 3) * 2;

    const float* Qp = Q + (size_t)(bh * TT + t0) * NN;
    const float* Kp = K + (size_t)(bh * TT + t0) * NN;
    const float* Vp = V + (size_t)(bh * TT + t0) * NN;
    const __nv_bfloat16* Sh = g_Sh + (size_t)(bh * NCH + ch) * (NN * NN);
    const __nv_bfloat16* Sl = g_Sl + (size_t)(bh * NCH + ch) * (NN * NN);

    int sr = tid >> 2, sc8 = tid & 3;
    uint32_t s_so = (uint32_t)(sr * 80 + sc8 * 16);
    int vr = tid >> 5, vc8 = tid & 31;
    uint32_t v_so = (uint32_t)(vr * 528 + vc8 * 16);

    // ---- staging lambdas -----------------------------------------------------
    uint4 qhi, qlo, khi, klo;
    auto loadQK = [&](int sl) {
        int f = sl * 32 + sc8 * 8;
        float4 c = *(const float4*)(g_tabc + (t0 + sr) * 128 + (f >> 1));
        float4 s = *(const float4*)(g_tabs + (t0 + sr) * 128 + (f >> 1));
        rope_split8_cs(Qp + (size_t)sr * NN + f, c, s, qhi, qlo);
        rope_split8_cs(Kp + (size_t)sr * NN + f, c, s, khi, klo);
    };
    auto storeQK = [&](int buf) {
        char* ab = sm + buf * AT_BUF_A;
        *(uint4*)(ab + s_so) = qhi;
        *(uint4*)(ab + 10240 + s_so) = qlo;
        char* bb = sm + AT_B0 + buf * AT_BUF_B;
        *(uint4*)(bb + s_so) = khi;
        *(uint4*)(bb + 16896 + s_so) = klo;
    };
    auto loadQ2 = [&](int sl) {
        int f = sl * 32 + sc8 * 8;
        float4 c = *(const float4*)(g_tabc + (t0 + sr) * 128 + (f >> 1));
        float4 s = *(const float4*)(g_tabs + (t0 + sr) * 128 + (f >> 1));
        rope_split8_cs(Qp + (size_t)sr * NN + f, c, s, qhi, qlo);
    };
    auto storeQ2 = [&](int buf) {
        char* ab = sm + buf * AT_BUF_A;
        *(uint4*)(ab + s_so) = qhi;
        *(uint4*)(ab + 10240 + s_so) = qlo;
    };
    auto cpS = [&](int buf, int sl) {
        uint32_t bb = sb + AT_B0 + buf * AT_BUF_B;
        int f0 = sl * 32;
#pragma unroll
        for (int v = tid; v < 1024; v += 512) {
            int r = v >> 5, c8 = v & 31;
            uint32_t so = (uint32_t)(r * 528 + c8 * 16);
            cpa16(bb + so,         Sh + (size_t)(f0 + r) * NN + c8 * 8);
            cpa16(bb + 16896 + so, Sl + (size_t)(f0 + r) * NN + c8 * 8);
        }
    };
    uint4 vhi0, vlo0, vhi1, vlo1;
    auto loadV3 = [&](int sl) {
        split8(Vp + (size_t)(sl * 32 + vr) * NN + vc8 * 8, vhi0, vlo0);
        split8(Vp + (size_t)(sl * 32 + vr + 16) * NN + vc8 * 8, vhi1, vlo1);
    };
    auto storeV3 = [&](int buf) {
        char* bb = sm + AT_B0 + buf * AT_BUF_B;
        *(uint4*)(bb + v_so) = vhi0;
        *(uint4*)(bb + 16896 + v_so) = vlo0;
        *(uint4*)(bb + 8448 + v_so) = vhi1;
        *(uint4*)(bb + 16896 + 8448 + v_so) = vlo1;
    };

    int pr = (S1_R_PACK >> (wid * 2)) & 3;
    int pc = (S1_C_PACK >> (wid * 2)) & 3;
    bool act1 = (wid < 10);

    // ======== Stage 1: P = QR @ KR^T, lower-triangle tiles only ================
    float acc1[2][4][4];
#pragma unroll
    for (int a = 0; a < 2; a++)
#pragma unroll
        for (int b = 0; b < 4; b++)
#pragma unroll
            for (int c = 0; c < 4; c++) acc1[a][b][c] = 0.f;

    loadQK(0);
    storeQK(0);
    __syncthreads();
    for (int sl = 0; sl < 8; sl++) {
        if (sl < 7) loadQK(sl + 1);
        else if (ch > 0) { cpS(0, 6); CP_COMMIT(); }   // S slab 6 -> buf0 (K buf0 dead)
        if (act1) {
            uint32_t ab = sb + (sl & 1) * AT_BUF_A;
            uint32_t bb = sb + AT_B0 + (sl & 1) * AT_BUF_B;
#pragma unroll
            for (int k0 = 0; k0 < 32; k0 += 16) {
                uint32_t ah[2][4], al[2][4];
#pragma unroll
                for (int mt = 0; mt < 2; mt++) {
                    uint32_t off = (uint32_t)(((pr * 32 + mt * 16 + lm16) * 40 +
                                               k0 + 8 * l16) * 2);
                    ldsm4(ah[mt], ab + off);
                    ldsm4(al[mt], ab + 10240 + off);
                }
#pragma unroll
                for (int np = 0; np < 2; np++) {
                    uint32_t bh2[4], bl2[4];
                    uint32_t off = (uint32_t)(((pc * 32 + np * 16 + lmod8 + 8 * l16) * 40 +
                                               k0 + 8 * l8) * 2);
                    ldsm4(bh2, bb + off);
                    ldsm4(bl2, bb + 16896 + off);
#pragma unroll
                    for (int mt = 0; mt < 2; mt++) {
                        mma_bf16(acc1[mt][2*np],   ah[mt], bh2);
                        mma_bf16(acc1[mt][2*np],   ah[mt], bl2);
                        mma_bf16(acc1[mt][2*np],   al[mt], bh2);
                        mma_bf16(acc1[mt][2*np+1], ah[mt], bh2 + 2);
                        mma_bf16(acc1[mt][2*np+1], ah[mt], bl2 + 2);
                        mma_bf16(acc1[mt][2*np+1], al[mt], bh2 + 2);
                    }
                }
            }
        }
        if (sl < 7) { storeQK((sl + 1) & 1); __syncthreads(); }
    }
    __syncthreads();                       // all sl=7 MMAs done (K buf1 free)
    if (ch > 0) { cpS(1, 7); CP_COMMIT(); }   // S slab 7 -> buf1, overlaps P writes
    else loadV3(0);                           // ch=0: prefetch stage-3 V

    // mask (strict lower triangle) + bf16 split into smem P (live tiles only)
    if (act1) {
#pragma unroll
        for (int mt = 0; mt < 2; mt++)
#pragma unroll
            for (int nt = 0; nt < 4; nt++)
#pragma unroll
                for (int h = 0; h < 2; h++) {
                    int rr = pr * 32 + mt * 16 + lq + 8 * h;
                    int cn = pc * 32 + nt * 8 + lr2;
                    float v0 = (cn     < rr) ? acc1[mt][nt][2*h]   : 0.f;
                    float v1 = (cn + 1 < rr) ? acc1[mt][nt][2*h+1] : 0.f;
                    uint32_t hbits, lbits;
                    split2(v0, v1, hbits, lbits);
                    uint32_t bo = (uint32_t)((rr * 136 + cn) * 2);
                    *(uint32_t*)(sm + AT_PH + bo) = hbits;
                    *(uint32_t*)(sm + AT_PL + bo) = lbits;
                }
    }
    if (ch > 0) CP_WAIT0();
    __syncthreads();

    // ======== Stage 2: D = QR @ S_pref, slab order {6,7,0..5} ==================
    float acc[2][8][4];
#pragma unroll
    for (int a = 0; a < 2; a++)
#pragma unroll
        for (int b = 0; b < 8; b++)
#pragma unroll
            for (int c = 0; c < 4; c++) acc[a][b][c] = 0.f;

    if (ch > 0) {
        for (int i = 0; i < 8; i++) {
            if (i >= 1 && i < 7) {
                int sn = (7 + i) & 7;               // next slab
                loadQ2(sn);
                cpS((i + 1) & 1, sn);
                CP_COMMIT();
            } else if (i == 7) loadV3(0);           // prefetch stage-3 V slab 0
            uint32_t ab = sb + (i & 1) * AT_BUF_A;
            uint32_t bb = sb + AT_B0 + (i & 1) * AT_BUF_B;
#pragma unroll
            for (int k0 = 0; k0 < 32; k0 += 16) {
                uint32_t ah[2][4], al[2][4];
#pragma unroll
                for (int mt = 0; mt < 2; mt++) {
                    uint32_t off = (uint32_t)(((wm * 32 + mt * 16 + lm16) * 40 +
                                               k0 + 8 * l16) * 2);
                    ldsm4(ah[mt], ab + off);
                    ldsm4(al[mt], ab + 10240 + off);
                }
#pragma unroll
                for (int np = 0; np < 4; np++) {
                    uint32_t bh2[4], bl2[4];
                    uint32_t off = (uint32_t)(((k0 + lmod8 + 8 * l8) * 264 +
                                               wn * 64 + np * 16 + 8 * l16) * 2);
                    ldsm4t(bh2, bb + off);
                    ldsm4t(bl2, bb + 16896 + off);
#pragma unroll
                    for (int mt = 0; mt < 2; mt++) {
                        mma_bf16(acc[mt][2*np],   ah[mt], bh2);
                        mma_bf16(acc[mt][2*np],   ah[mt], bl2);
                        mma_bf16(acc[mt][2*np],   al[mt], bh2);
                        mma_bf16(acc[mt][2*np+1], ah[mt], bh2 + 2);
                        mma_bf16(acc[mt][2*np+1], ah[mt], bl2 + 2);
                        mma_bf16(acc[mt][2*np+1], al[mt], bh2 + 2);
                    }
                }
            }
            if (i < 7) {
                if (i >= 1) storeQ2((i + 1) & 1);
                CP_WAIT0();
                __syncthreads();
            }
        }
    }

    // ======== Stage 3: D += P @ V — skip slabs above warp's diagonal ===========
    storeV3(0);                            // buf0 free (last read at i=6 / ch=0: stage1 sl=6)
    __syncthreads();
    for (int sl = 0; sl < 4; sl++) {
        if (sl < 3) loadV3(sl + 1);
        if (sl <= wm) {
            int s0 = sl * 32;
            uint32_t bb = sb + AT_B0 + (sl & 1) * AT_BUF_B;
#pragma unroll
            for (int k0 = 0; k0 < 32; k0 += 16) {
                uint32_t ah[2][4], al[2][4];
#pragma unroll
                for (int mt = 0; mt < 2; mt++) {
                    uint32_t off = (uint32_t)(((wm * 32 + mt * 16 + lm16) * 136 +
                                               s0 + k0 + 8 * l16) * 2);
                    ldsm4(ah[mt], sb + AT_PH + off);
                    ldsm4(al[mt], sb + AT_PL + off);
                }
#pragma unroll
                for (int np = 0; np < 4; np++) {
                    uint32_t bh2[4], bl2[4];
                    uint32_t off = (uint32_t)(((k0 + lmod8 + 8 * l8) * 264 +
                                               wn * 64 + np * 16 + 8 * l16) * 2);
                    ldsm4t(bh2, bb + off);
                    ldsm4t(bl2, bb + 16896 + off);
#pragma unroll
                    for (int mt = 0; mt < 2; mt++) {
                        mma_bf16(acc[mt][2*np],   ah[mt], bh2);
                        mma_bf16(acc[mt][2*np],   ah[mt], bl2);
                        mma_bf16(acc[mt][2*np],   al[mt], bh2);
                        mma_bf16(acc[mt][2*np+1], ah[mt], bh2 + 2);
                        mma_bf16(acc[mt][2*np+1], ah[mt], bl2 + 2);
                        mma_bf16(acc[mt][2*np+1], al[mt], bh2 + 2);
                    }
                }
            }
        }
        if (sl < 3) { storeV3((sl + 1) & 1); __syncthreads(); }
    }

    // epilogue
#pragma unroll
    for (int mt = 0; mt < 2; mt++)
#pragma unroll
        for (int nt = 0; nt < 8; nt++)
#pragma unroll
            for (int h = 0; h < 2; h++) {
                int rr = wm * 32 + mt * 16 + lq + 8 * h;
                int cc = wn * 64 + nt * 8 + lr2;
                float2 o; o.x = acc[mt][nt][2*h]; o.y = acc[mt][nt][2*h+1];
                *(float2*)(out + (size_t)(bh * TT + t0 + rr) * NN + cc) = o;
            }
}

// ---------------- launcher -------------------------------------------------------
extern "C" void kernel_launch(void* const* d_in, const int* in_sizes, int n_in,
                              void* d_out, int out_size) {
    const float* Q = (const float*)d_in[0];
    const float* K = (const float*)d_in[1];
    const float* V = (const float*)d_in[2];
    float* out = (float*)d_out;

    static bool attr_set = false;
    if (!attr_set) {
        cudaFuncSetAttribute(k_kv,   cudaFuncAttributeMaxDynamicSharedMemorySize, SMEM_KV);
        cudaFuncSetAttribute(k_attn, cudaFuncAttributeMaxDynamicSharedMemorySize, SMEM_ATTN);
        attr_set = true;
    }

    k_tables<<<512, 512>>>();
    k_kv<<<dim3(BH * (NCH - 1), 2), 512, SMEM_KV>>>(K, V);
    k_scan<<<(BH * NN * NN / 4 + 255) / 256, 256>>>();
    k_attn<<<BH * NCH, 512, SMEM_ATTN>>>(Q, K, V, out);
}